// round 13
// baseline (speedup 1.0000x reference)
#include <cuda_runtime.h>
#include <cuda_bf16.h>
#include <math.h>
#include <stdint.h>

#define SS 1024
#define BB 16
#define DD 512
#define HH 8
#define KK 64

using ull = unsigned long long;

// bf16 hi/lo splits of inputs & weights (for proj / outproj GEMMs)
__device__ __nv_bfloat16 g_ih[3 * SS * BB * DD];   // q,k,v inputs [t][m=s*16+b][d]
__device__ __nv_bfloat16 g_il[3 * SS * BB * DD];
__device__ __nv_bfloat16 g_wh[3 * DD * DD];        // WQ,WK,WV [t][n][d]
__device__ __nv_bfloat16 g_wl[3 * DD * DD];
__device__ __nv_bfloat16 g_oh[DD * DD];            // Wout [n][j]
__device__ __nv_bfloat16 g_ol[DD * DD];
// normalized projections, bf16, [bh][s][k]  (K hi only; V hi+lo)
__device__ __nv_bfloat16 g_qh[BB * HH * SS * KK];
__device__ __nv_bfloat16 g_kh[BB * HH * SS * KK];
__device__ __nv_bfloat16 g_vh[BB * HH * SS * KK];
__device__ __nv_bfloat16 g_vl[BB * HH * SS * KK];
// attention output [m = s*16+b][j = h*64+k], bf16 hi/lo
__device__ __nv_bfloat16 g_ath[SS * BB * HH * KK];
__device__ __nv_bfloat16 g_atl[SS * BB * HH * KK];

// ---------------------------------------------------------------------------
// helpers
// ---------------------------------------------------------------------------
__device__ __forceinline__ uint32_t smem_u32(const void* p) {
    uint32_t a;
    asm("{ .reg .u64 t; cvta.to.shared.u64 t, %1; cvt.u32.u64 %0, t; }"
        : "=r"(a) : "l"(p));
    return a;
}

__device__ __forceinline__ unsigned bpack(float lo_elem, float hi_elem) {
    unsigned r;  // lower 16 = bf16(lo_elem), upper 16 = bf16(hi_elem)
    asm("cvt.rn.bf16x2.f32 %0, %1, %2;" : "=r"(r) : "f"(hi_elem), "f"(lo_elem));
    return r;
}
__device__ __forceinline__ void split2(float x, float y, unsigned& hi, unsigned& lo) {
    unsigned h = bpack(x, y);
    float hx = __uint_as_float(h << 16);
    float hy = __uint_as_float(h & 0xffff0000u);
    hi = h;
    lo = bpack(x - hx, y - hy);
}

__device__ __forceinline__ void ldsm4(unsigned* r, uint32_t addr) {
    asm volatile("ldmatrix.sync.aligned.m8n8.x4.shared.b16 {%0,%1,%2,%3}, [%4];"
                 : "=r"(r[0]), "=r"(r[1]), "=r"(r[2]), "=r"(r[3]) : "r"(addr));
}
__device__ __forceinline__ void ldsm4t(unsigned* r, uint32_t addr) {
    asm volatile("ldmatrix.sync.aligned.m8n8.x4.trans.shared.b16 {%0,%1,%2,%3}, [%4];"
                 : "=r"(r[0]), "=r"(r[1]), "=r"(r[2]), "=r"(r[3]) : "r"(addr));
}
// non-volatile: pure register computation, lets ptxas interleave MMAs.
__device__ __forceinline__ void mma16816(float* d, const unsigned* a, const unsigned* b) {
    asm("mma.sync.aligned.m16n8k16.row.col.f32.bf16.bf16.f32 "
        "{%0,%1,%2,%3}, {%4,%5,%6,%7}, {%8,%9}, {%0,%1,%2,%3};"
        : "+f"(d[0]), "+f"(d[1]), "+f"(d[2]), "+f"(d[3])
        : "r"(a[0]), "r"(a[1]), "r"(a[2]), "r"(a[3]), "r"(b[0]), "r"(b[1]));
}
__device__ __forceinline__ void cpasync16(uint32_t saddr, const void* gaddr) {
    asm volatile("cp.async.ca.shared.global [%0], [%1], 16;"
                 :: "r"(saddr), "l"(gaddr) : "memory");
}
#define CP_COMMIT() asm volatile("cp.async.commit_group;" ::: "memory")
#define CP_WAIT(n)  asm volatile("cp.async.wait_group %0;" :: "n"(n) : "memory")

// GEMM smem: 4-stage ring, KC=16 per stage.
// Row = 16 bf16 = 32B, padded to 48B (16B-aligned, ldmatrix conflict-free:
// stride 12 words -> 8-row phases hit distinct bank quads).
#define ROW_B    48
#define ARR_B    6144            // 128 rows * 48B
#define STAGE_B  24576           // Ahi | Alo | Bhi | Blo
#define MMA_SMEM (4 * STAGE_B)   // 98304 -> still 2 CTAs/SM

// ---------------------------------------------------------------------------
// fused convert: fp32 -> bf16 hi/lo, one launch, z selects array
// ---------------------------------------------------------------------------
__global__ void cvt_all(const float4* __restrict__ q, const float4* __restrict__ k,
                        const float4* __restrict__ v, const float4* __restrict__ wq,
                        const float4* __restrict__ wk, const float4* __restrict__ wv,
                        const float4* __restrict__ wo)
{
    const int NIN = SS * BB * DD / 4, NW = DD * DD / 4;
    const int z = blockIdx.z;
    const float4* src;
    uint2 *hi, *lo;
    int n4;
    switch (z) {
        case 0: src = q;  hi = (uint2*)g_ih;                 lo = (uint2*)g_il;                 n4 = NIN; break;
        case 1: src = k;  hi = (uint2*)g_ih + NIN;           lo = (uint2*)g_il + NIN;           n4 = NIN; break;
        case 2: src = v;  hi = (uint2*)g_ih + 2 * NIN;       lo = (uint2*)g_il + 2 * NIN;       n4 = NIN; break;
        case 3: src = wq; hi = (uint2*)g_wh;                 lo = (uint2*)g_wl;                 n4 = NW;  break;
        case 4: src = wk; hi = (uint2*)g_wh + NW;            lo = (uint2*)g_wl + NW;            n4 = NW;  break;
        case 5: src = wv; hi = (uint2*)g_wh + 2 * NW;        lo = (uint2*)g_wl + 2 * NW;        n4 = NW;  break;
        default: src = wo; hi = (uint2*)g_oh;                lo = (uint2*)g_ol;                 n4 = NW;  break;
    }
    for (int i = blockIdx.x * blockDim.x + threadIdx.x; i < n4;
         i += gridDim.x * blockDim.x) {
        float4 x = src[i];
        unsigned h0, l0, h1, l1;
        split2(x.x, x.y, h0, l0);
        split2(x.z, x.w, h1, l1);
        hi[i] = make_uint2(h0, h1);
        lo[i] = make_uint2(l0, l1);
    }
}

// ---------------------------------------------------------------------------
// shared mma mainloop: 128x128 fp32 tile in d[2][8][4] (3-term hi/lo)
// 4-stage cp.async ring, 3-stage lookahead, 1 barrier/iter, 32 iters (KC=16).
// ---------------------------------------------------------------------------
struct MmaCtx {
    float d[2][8][4];
    uint32_t aHi[2], aLo[2], bHi[4], bLo[4];
};

__device__ __forceinline__ void mma_mainloop(
    MmaCtx& cx, uint32_t sb,
    const __nv_bfloat16* srcAh, const __nv_bfloat16* srcAl,
    const __nv_bfloat16* srcBh, const __nv_bfloat16* srcBl)
{
    const int tid = threadIdx.x;
    const int wid = tid >> 5, lane = tid & 31;
    const int wm = (wid & 3) * 32, wn = (wid >> 2) * 64;

    #pragma unroll
    for (int mb = 0; mb < 2; mb++) {
        uint32_t ro = (uint32_t)(wm + mb * 16 + (lane & 15)) * ROW_B + (lane >> 4) * 16;
        cx.aHi[mb] = sb + ro;
        cx.aLo[mb] = sb + ARR_B + ro;
    }
    #pragma unroll
    for (int p = 0; p < 4; p++) {
        uint32_t ro = (uint32_t)(wn + p * 16 + (lane >> 4) * 8 + (lane & 7)) * ROW_B
                    + ((lane >> 3) & 1) * 16;
        cx.bHi[p] = sb + 2 * ARR_B + ro;
        cx.bLo[p] = sb + 3 * ARR_B + ro;
    }
    #pragma unroll
    for (int mb = 0; mb < 2; mb++)
        #pragma unroll
        for (int nb = 0; nb < 8; nb++)
            #pragma unroll
            for (int e = 0; e < 4; e++) cx.d[mb][nb][e] = 0.f;

    // per-thread loader coords: 1 chunk per array per stage
    const int lr = tid >> 1;           // row 0..127
    const int lc = tid & 1;            // 16B half of the 32B row
    const uint32_t ldst = (uint32_t)(lr * ROW_B + lc * 16);
    const size_t lgo = (size_t)lr * DD + lc * 8;

    auto load_stage = [&](int st, int k0) {
        uint32_t stb = sb + (uint32_t)st * STAGE_B + ldst;
        cpasync16(stb,             srcAh + lgo + k0);
        cpasync16(stb + ARR_B,     srcAl + lgo + k0);
        cpasync16(stb + 2 * ARR_B, srcBh + lgo + k0);
        cpasync16(stb + 3 * ARR_B, srcBl + lgo + k0);
        CP_COMMIT();
    };

    load_stage(0, 0);
    load_stage(1, 16);
    load_stage(2, 32);

    for (int it = 0; it < 32; it++) {
        if (it + 2 < 32)      { CP_WAIT(2); }
        else if (it + 1 < 32) { CP_WAIT(1); }
        else                  { CP_WAIT(0); }
        __syncthreads();      // stage `it` visible to all; all done with it-1
        if (it + 3 < 32) load_stage((it + 3) & 3, (it + 3) * 16);

        const uint32_t so = (uint32_t)(it & 3) * STAGE_B;
        unsigned ah[2][4], al[2][4];
        #pragma unroll
        for (int mb = 0; mb < 2; mb++) {
            ldsm4(ah[mb], cx.aHi[mb] + so);
            ldsm4(al[mb], cx.aLo[mb] + so);
        }
        #pragma unroll
        for (int p = 0; p < 4; p++) {
            unsigned tbh[4], tbl[4];
            ldsm4(tbh, cx.bHi[p] + so);
            ldsm4(tbl, cx.bLo[p] + so);
            // term-major: 4 independent accumulators between reuses
            #pragma unroll
            for (int mb = 0; mb < 2; mb++)
                #pragma unroll
                for (int qn = 0; qn < 2; qn++)
                    mma16816(cx.d[mb][2 * p + qn], ah[mb], &tbh[2 * qn]);
            #pragma unroll
            for (int mb = 0; mb < 2; mb++)
                #pragma unroll
                for (int qn = 0; qn < 2; qn++)
                    mma16816(cx.d[mb][2 * p + qn], ah[mb], &tbl[2 * qn]);
            #pragma unroll
            for (int mb = 0; mb < 2; mb++)
                #pragma unroll
                for (int qn = 0; qn < 2; qn++)
                    mma16816(cx.d[mb][2 * p + qn], al[mb], &tbh[2 * qn]);
        }
    }
}

// ---------------------------------------------------------------------------
// projection + L2 norm -> bf16 outputs in [bh][s][k]
// ---------------------------------------------------------------------------
__global__ __launch_bounds__(256) void proj_mma()
{
    extern __shared__ __align__(16) char dsm[];
    const uint32_t sb = smem_u32(dsm);

    const int n0 = blockIdx.x * 128;
    const int m0 = blockIdx.y * 128;
    const int t  = n0 >> 9;
    const int nr = n0 & 511;

    const __nv_bfloat16* srcAh = g_ih + (size_t)t * (SS * BB * DD) + (size_t)m0 * DD;
    const __nv_bfloat16* srcAl = g_il + (size_t)t * (SS * BB * DD) + (size_t)m0 * DD;
    const __nv_bfloat16* srcBh = g_wh + (size_t)t * (DD * DD) + (size_t)nr * DD;
    const __nv_bfloat16* srcBl = g_wl + (size_t)t * (DD * DD) + (size_t)nr * DD;

    __nv_bfloat16* dsth = (t == 0) ? g_qh : (t == 1) ? g_kh : g_vh;
    __nv_bfloat16* dstl = g_vl;
    const bool write_lo = (t == 2);     // only V needs the lo residue

    MmaCtx cx;
    mma_mainloop(cx, sb, srcAh, srcAl, srcBh, srcBl);

    const int tid = threadIdx.x;
    const int wid = tid >> 5, lane = tid & 31;
    const int wm = (wid & 3) * 32, wn = (wid >> 2) * 64;
    const int r0 = lane >> 2, c0 = lane & 3;
    const int h = (nr >> 6) + (wn >> 6);

    #pragma unroll
    for (int mb = 0; mb < 2; mb++) {
        float ssa = 0.f, ssb = 0.f;
        #pragma unroll
        for (int nb = 0; nb < 8; nb++) {
            float* d = cx.d[mb][nb];
            ssa = fmaf(d[0], d[0], fmaf(d[1], d[1], ssa));
            ssb = fmaf(d[2], d[2], fmaf(d[3], d[3], ssb));
        }
        ssa += __shfl_xor_sync(0xffffffffu, ssa, 1);
        ssa += __shfl_xor_sync(0xffffffffu, ssa, 2);
        ssb += __shfl_xor_sync(0xffffffffu, ssb, 1);
        ssb += __shfl_xor_sync(0xffffffffu, ssb, 2);
        float inva = 1.0f / fmaxf(sqrtf(ssa), 1e-12f);
        float invb = 1.0f / fmaxf(sqrtf(ssb), 1e-12f);

        int ma = m0 + wm + mb * 16 + r0;
        int mb2 = ma + 8;
        int ba = ma & 15, sa = ma >> 4;
        int bbb = mb2 & 15, sbb = mb2 >> 4;
        size_t rowA = (((size_t)(ba * HH + h)) * SS + sa) * KK;
        size_t rowB = (((size_t)(bbb * HH + h)) * SS + sbb) * KK;
        #pragma unroll
        for (int nb = 0; nb < 8; nb++) {
            int kk = ((wn & 63) + nb * 8 + 2 * c0);
            float* d = cx.d[mb][nb];
            unsigned hA, lA, hB, lB;
            split2(d[0] * inva, d[1] * inva, hA, lA);
            split2(d[2] * invb, d[3] * invb, hB, lB);
            *(unsigned*)&dsth[rowA + kk] = hA;
            *(unsigned*)&dsth[rowB + kk] = hB;
            if (write_lo) {
                *(unsigned*)&dstl[rowA + kk] = lA;
                *(unsigned*)&dstl[rowB + kk] = lB;
            }
        }
    }
}

// ---------------------------------------------------------------------------
// output projection: out[m][n] fp32
// ---------------------------------------------------------------------------
__global__ __launch_bounds__(256) void outproj_mma(float* __restrict__ out)
{
    extern __shared__ __align__(16) char dsm[];
    const uint32_t sb = smem_u32(dsm);

    const int n0 = blockIdx.x * 128;
    const int m0 = blockIdx.y * 128;

    MmaCtx cx;
    mma_mainloop(cx, sb, g_ath + (size_t)m0 * DD, g_atl + (size_t)m0 * DD,
                 g_oh + (size_t)n0 * DD, g_ol + (size_t)n0 * DD);

    const int tid = threadIdx.x;
    const int wid = tid >> 5, lane = tid & 31;
    const int wm = (wid & 3) * 32, wn = (wid >> 2) * 64;
    const int r0 = lane >> 2, c0 = lane & 3;

    #pragma unroll
    for (int mb = 0; mb < 2; mb++) {
        int ma = m0 + wm + mb * 16 + r0;
        float* pa = out + (size_t)ma * DD;
        float* pb = out + (size_t)(ma + 8) * DD;
        #pragma unroll
        for (int nb = 0; nb < 8; nb++) {
            int n = n0 + wn + nb * 8 + 2 * c0;
            float* d = cx.d[mb][nb];
            *(float2*)&pa[n] = make_float2(d[0], d[1]);
            *(float2*)&pb[n] = make_float2(d[2], d[3]);
        }
    }
}

// ---------------------------------------------------------------------------
// attention via mma.sync: 128 q-rows per CTA, 8 warps x 16 rows, t-chunks 64.
// scores = Qh·Kh; P = exp(s/8) hi+lo; O += Ph·(Vh+Vl) + Pl·Vh.
// 3-stage cp.async ring (kh,vh,vl per stage), single sync per chunk.
// ---------------------------------------------------------------------------
#define AT_ROW   144
#define AT_ARR   (64 * AT_ROW)        // 9216
#define AT_STAGE (3 * AT_ARR)         // 27648
#define AT_QOFF  (3 * AT_STAGE)       // 82944
#define ATT_SMEM (AT_QOFF + 128 * AT_ROW)   // 101376

__global__ __launch_bounds__(256, 2) void attn_mma()
{
    extern __shared__ __align__(16) char dsm[];
    const uint32_t sb = smem_u32(dsm);

    const int tid = threadIdx.x, wid = tid >> 5, lane = tid & 31;
    const int s0 = blockIdx.x * 128;
    const int bh = blockIdx.y;
    const int b = bh >> 3, h = bh & 7;

    const __nv_bfloat16* qh = g_qh + (size_t)bh * SS * KK + (size_t)s0 * KK;
    const __nv_bfloat16* kh = g_kh + (size_t)bh * SS * KK;
    const __nv_bfloat16* vh = g_vh + (size_t)bh * SS * KK;
    const __nv_bfloat16* vl = g_vl + (size_t)bh * SS * KK;

    // chunk loader: kh,vh,vl tiles of 64 rows x 64 bf16 (6 chunks/thread)
    auto load_chunk = [&](uint32_t stb, int t0) {
        #pragma unroll
        for (int i = 0; i < 6; i++) {
            int idx = tid + i * 256;
            int a = idx >> 9, ci = idx & 511, r = ci >> 3, c = ci & 7;
            const __nv_bfloat16* s = (a == 0) ? kh : (a == 1) ? vh : vl;
            cpasync16(stb + a * AT_ARR + (uint32_t)(r * AT_ROW + c * 16),
                      s + (size_t)(t0 + r) * KK + c * 8);
        }
    };

    // group 0: Q tile (hi only), 128 rows x 64 bf16
    #pragma unroll
    for (int i = 0; i < 4; i++) {
        int idx = tid + i * 256;
        int r = idx >> 3, c = idx & 7;
        cpasync16(sb + AT_QOFF + (uint32_t)(r * AT_ROW + c * 16),
                  qh + (size_t)r * KK + c * 8);
    }
    CP_COMMIT();
    // groups 1,2: chunks 0,1
    load_chunk(sb, 0); CP_COMMIT();
    load_chunk(sb + AT_STAGE, 64); CP_COMMIT();

    CP_WAIT(2);          // Q ready
    __syncthreads();
    unsigned qf[4][4];
    const int wq0 = wid * 16;
    #pragma unroll
    for (int ks = 0; ks < 4; ks++)
        ldsm4(qf[ks], sb + AT_QOFF + (uint32_t)((wq0 + (lane & 15)) * AT_ROW)
                        + ks * 32 + (lane >> 4) * 16);

    float o[8][4] = {};
    float l0 = 0.f, l1 = 0.f;

    for (int c = 0; c < 16; c++) {
        if (c < 15) { CP_WAIT(1); } else { CP_WAIT(0); }
        __syncthreads();                 // all warps done with stage (c+2)%3's prior use
        if (c + 2 < 16) {
            load_chunk(sb + (uint32_t)((c + 2) % 3) * AT_STAGE, (c + 2) * 64);
            CP_COMMIT();
        }
        const uint32_t so = sb + (uint32_t)(c % 3) * AT_STAGE;

        // scores: Qh . Kh — p-pairs: 4 independent accumulators in flight
        float sc[8][4] = {};
        #pragma unroll
        for (int ks = 0; ks < 4; ks++) {
            #pragma unroll
            for (int pp = 0; pp < 2; pp++) {
                unsigned kh4a[4], kh4b[4];
                uint32_t roa = (uint32_t)(((2 * pp) * 16 + (lane >> 4) * 8 + (lane & 7)) * AT_ROW)
                             + ks * 32 + ((lane >> 3) & 1) * 16;
                uint32_t rob = roa + 16 * AT_ROW;
                ldsm4(kh4a, so + roa);
                ldsm4(kh4b, so + rob);
                mma16816(sc[4 * pp + 0], qf[ks], &kh4a[0]);
                mma16816(sc[4 * pp + 1], qf[ks], &kh4a[2]);
                mma16816(sc[4 * pp + 2], qf[ks], &kh4b[0]);
                mma16816(sc[4 * pp + 3], qf[ks], &kh4b[2]);
            }
        }

        // exp (bounded scores -> no running max), row sums
        float ev[8][4];
        #pragma unroll
        for (int nt = 0; nt < 8; nt++) {
            ev[nt][0] = __expf(sc[nt][0] * 0.125f);
            ev[nt][1] = __expf(sc[nt][1] * 0.125f);
            ev[nt][2] = __expf(sc[nt][2] * 0.125f);
            ev[nt][3] = __expf(sc[nt][3] * 0.125f);
            l0 += ev[nt][0] + ev[nt][1];
            l1 += ev[nt][2] + ev[nt][3];
        }

        // O += Ph·(Vh+Vl) + Pl·Vh — p-pairs, term-major (4 indep accs per term)
        #pragma unroll
        for (int ts = 0; ts < 4; ts++) {
            unsigned ph[4], pl[4];
            split2(ev[2 * ts][0],     ev[2 * ts][1],     ph[0], pl[0]);
            split2(ev[2 * ts][2],     ev[2 * ts][3],     ph[1], pl[1]);
            split2(ev[2 * ts + 1][0], ev[2 * ts + 1][1], ph[2], pl[2]);
            split2(ev[2 * ts + 1][2], ev[2 * ts + 1][3], ph[3], pl[3]);
            #pragma unroll
            for (int pp = 0; pp < 2; pp++) {
                uint32_t roa = (uint32_t)((ts * 16 + ((lane >> 3) & 1) * 8 + (lane & 7)) * AT_ROW)
                             + ((2 * pp) * 16 + (lane >> 4) * 8) * 2;
                uint32_t rob = roa + 32;
                unsigned vh4a[4], vl4a[4], vh4b[4], vl4b[4];
                ldsm4t(vh4a, so + 1 * AT_ARR + roa);
                ldsm4t(vl4a, so + 2 * AT_ARR + roa);
                ldsm4t(vh4b, so + 1 * AT_ARR + rob);
                ldsm4t(vl4b, so + 2 * AT_ARR + rob);
                // term 1: Ph . Vh
                mma16816(o[4 * pp + 0], ph, &vh4a[0]);
                mma16816(o[4 * pp + 1], ph, &vh4a[2]);
                mma16816(o[4 * pp + 2], ph, &vh4b[0]);
                mma16816(o[4 * pp + 3], ph, &vh4b[2]);
                // term 2: Ph . Vl
                mma16816(o[4 * pp + 0], ph, &vl4a[0]);
                mma16816(o[4 * pp + 1], ph, &vl4a[2]);
                mma16816(o[4 * pp + 2], ph, &vl4b[0]);
                mma16816(o[4 * pp + 3], ph, &vl4b[2]);
                // term 3: Pl . Vh
                mma16816(o[4 * pp + 0], pl, &vh4a[0]);
                mma16816(o[4 * pp + 1], pl, &vh4a[2]);
                mma16816(o[4 * pp + 2], pl, &vh4b[0]);
                mma16816(o[4 * pp + 3], pl, &vh4b[2]);
            }
        }
    }

    // softmax denominators: reduce col-pairs across the quad
    l0 += __shfl_xor_sync(0xffffffffu, l0, 1);
    l0 += __shfl_xor_sync(0xffffffffu, l0, 2);
    l1 += __shfl_xor_sync(0xffffffffu, l1, 1);
    l1 += __shfl_xor_sync(0xffffffffu, l1, 2);
    float inv0 = 1.0f / l0, inv1 = 1.0f / l1;

    const int r0 = lane >> 2, c0 = lane & 3;
    int sA = s0 + wq0 + r0;
    size_t mA = ((size_t)sA * BB + b) * (HH * KK);
    size_t mB = ((size_t)(sA + 8) * BB + b) * (HH * KK);
    #pragma unroll
    for (int nk = 0; nk < 8; nk++) {
        int j = h * KK + nk * 8 + 2 * c0;
        unsigned h0, lo0, h1, lo1;
        split2(o[nk][0] * inv0, o[nk][1] * inv0, h0, lo0);
        split2(o[nk][2] * inv1, o[nk][3] * inv1, h1, lo1);
        *(unsigned*)&g_ath[mA + j] = h0;
        *(unsigned*)&g_atl[mA + j] = lo0;
        *(unsigned*)&g_ath[mB + j] = h1;
        *(unsigned*)&g_atl[mB + j] = lo1;
    }
}

// ---------------------------------------------------------------------------
extern "C" void kernel_launch(void* const* d_in, const int* in_sizes, int n_in,
                              void* d_out, int out_size)
{
    const float* q    = (const float*)d_in[0];
    const float* k    = (const float*)d_in[1];
    const float* v    = (const float*)d_in[2];
    const float* WQ   = (const float*)d_in[3];
    const float* WK   = (const float*)d_in[4];
    const float* WV   = (const float*)d_in[5];
    const float* Wout = (const float*)d_in[6];
    float* out = (float*)d_out;

    cudaFuncSetAttribute(proj_mma,
                         cudaFuncAttributeMaxDynamicSharedMemorySize, MMA_SMEM);
    cudaFuncSetAttribute(outproj_mma,
                         cudaFuncAttributeMaxDynamicSharedMemorySize, MMA_SMEM);
    cudaFuncSetAttribute(attn_mma,
                         cudaFuncAttributeMaxDynamicSharedMemorySize, ATT_SMEM);

    cvt_all<<<dim3(1024, 1, 7), 256>>>((const float4*)q, (const float4*)k,
                                       (const float4*)v, (const float4*)WQ,
                                       (const float4*)WK, (const float4*)WV,
                                       (const float4*)Wout);
    proj_mma<<<dim3(12, 128), 256, MMA_SMEM>>>();
    attn_mma<<<dim3(SS / 128, BB * HH), 256, ATT_SMEM>>>();
    outproj_mma<<<dim3(4, 128), 256, MMA_SMEM>>>(out);
}

// round 14
// speedup vs baseline: 1.0983x; 1.0983x over previous
#include <cuda_runtime.h>
#include <cuda_bf16.h>
#include <math.h>
#include <stdint.h>

#define SS 1024
#define BB 16
#define DD 512
#define HH 8
#define KK 64

using ull = unsigned long long;

// bf16 hi/lo splits of inputs & weights (for proj / outproj GEMMs)
__device__ __nv_bfloat16 g_ih[3 * SS * BB * DD];   // q,k,v inputs [t][m=s*16+b][d]
__device__ __nv_bfloat16 g_il[3 * SS * BB * DD];
__device__ __nv_bfloat16 g_wh[3 * DD * DD];        // WQ,WK,WV [t][n][d]
__device__ __nv_bfloat16 g_wl[3 * DD * DD];
__device__ __nv_bfloat16 g_oh[DD * DD];            // Wout [n][j]
__device__ __nv_bfloat16 g_ol[DD * DD];
// normalized projections, bf16, [bh][s][k]  (K hi only; V hi+lo)
__device__ __nv_bfloat16 g_qh[BB * HH * SS * KK];
__device__ __nv_bfloat16 g_kh[BB * HH * SS * KK];
__device__ __nv_bfloat16 g_vh[BB * HH * SS * KK];
__device__ __nv_bfloat16 g_vl[BB * HH * SS * KK];
// attention output [m = s*16+b][j = h*64+k], bf16 hi/lo
__device__ __nv_bfloat16 g_ath[SS * BB * HH * KK];
__device__ __nv_bfloat16 g_atl[SS * BB * HH * KK];

// ---------------------------------------------------------------------------
// helpers
// ---------------------------------------------------------------------------
__device__ __forceinline__ uint32_t smem_u32(const void* p) {
    uint32_t a;
    asm("{ .reg .u64 t; cvta.to.shared.u64 t, %1; cvt.u32.u64 %0, t; }"
        : "=r"(a) : "l"(p));
    return a;
}

__device__ __forceinline__ unsigned bpack(float lo_elem, float hi_elem) {
    unsigned r;  // lower 16 = bf16(lo_elem), upper 16 = bf16(hi_elem)
    asm("cvt.rn.bf16x2.f32 %0, %1, %2;" : "=r"(r) : "f"(hi_elem), "f"(lo_elem));
    return r;
}
__device__ __forceinline__ void split2(float x, float y, unsigned& hi, unsigned& lo) {
    unsigned h = bpack(x, y);
    float hx = __uint_as_float(h << 16);
    float hy = __uint_as_float(h & 0xffff0000u);
    hi = h;
    lo = bpack(x - hx, y - hy);
}

__device__ __forceinline__ void ldsm4(unsigned* r, uint32_t addr) {
    asm volatile("ldmatrix.sync.aligned.m8n8.x4.shared.b16 {%0,%1,%2,%3}, [%4];"
                 : "=r"(r[0]), "=r"(r[1]), "=r"(r[2]), "=r"(r[3]) : "r"(addr));
}
__device__ __forceinline__ void ldsm4t(unsigned* r, uint32_t addr) {
    asm volatile("ldmatrix.sync.aligned.m8n8.x4.trans.shared.b16 {%0,%1,%2,%3}, [%4];"
                 : "=r"(r[0]), "=r"(r[1]), "=r"(r[2]), "=r"(r[3]) : "r"(addr));
}
// non-volatile: pure register computation, lets ptxas interleave MMAs.
__device__ __forceinline__ void mma16816(float* d, const unsigned* a, const unsigned* b) {
    asm("mma.sync.aligned.m16n8k16.row.col.f32.bf16.bf16.f32 "
        "{%0,%1,%2,%3}, {%4,%5,%6,%7}, {%8,%9}, {%0,%1,%2,%3};"
        : "+f"(d[0]), "+f"(d[1]), "+f"(d[2]), "+f"(d[3])
        : "r"(a[0]), "r"(a[1]), "r"(a[2]), "r"(a[3]), "r"(b[0]), "r"(b[1]));
}
__device__ __forceinline__ void cpasync16(uint32_t saddr, const void* gaddr) {
    asm volatile("cp.async.ca.shared.global [%0], [%1], 16;"
                 :: "r"(saddr), "l"(gaddr) : "memory");
}
#define CP_COMMIT() asm volatile("cp.async.commit_group;" ::: "memory")
#define CP_WAIT(n)  asm volatile("cp.async.wait_group %0;" :: "n"(n) : "memory")

// GEMM smem: 4-stage ring, KC=16 per stage.
// Row = 16 bf16 = 32B, padded to 48B (16B-aligned, ldmatrix conflict-free:
// stride 12 words -> 8-row phases hit distinct bank quads).
#define ROW_B    48
#define ARR_B    6144            // 128 rows * 48B
#define STAGE_B  24576           // Ahi | Alo | Bhi | Blo
#define MMA_SMEM (4 * STAGE_B)   // 98304 -> 2 CTAs/SM (with regs capped at 128)

// ---------------------------------------------------------------------------
// fused convert: fp32 -> bf16 hi/lo, one launch, z selects array
// ---------------------------------------------------------------------------
__global__ void cvt_all(const float4* __restrict__ q, const float4* __restrict__ k,
                        const float4* __restrict__ v, const float4* __restrict__ wq,
                        const float4* __restrict__ wk, const float4* __restrict__ wv,
                        const float4* __restrict__ wo)
{
    const int NIN = SS * BB * DD / 4, NW = DD * DD / 4;
    const int z = blockIdx.z;
    const float4* src;
    uint2 *hi, *lo;
    int n4;
    switch (z) {
        case 0: src = q;  hi = (uint2*)g_ih;                 lo = (uint2*)g_il;                 n4 = NIN; break;
        case 1: src = k;  hi = (uint2*)g_ih + NIN;           lo = (uint2*)g_il + NIN;           n4 = NIN; break;
        case 2: src = v;  hi = (uint2*)g_ih + 2 * NIN;       lo = (uint2*)g_il + 2 * NIN;       n4 = NIN; break;
        case 3: src = wq; hi = (uint2*)g_wh;                 lo = (uint2*)g_wl;                 n4 = NW;  break;
        case 4: src = wk; hi = (uint2*)g_wh + NW;            lo = (uint2*)g_wl + NW;            n4 = NW;  break;
        case 5: src = wv; hi = (uint2*)g_wh + 2 * NW;        lo = (uint2*)g_wl + 2 * NW;        n4 = NW;  break;
        default: src = wo; hi = (uint2*)g_oh;                lo = (uint2*)g_ol;                 n4 = NW;  break;
    }
    for (int i = blockIdx.x * blockDim.x + threadIdx.x; i < n4;
         i += gridDim.x * blockDim.x) {
        float4 x = src[i];
        unsigned h0, l0, h1, l1;
        split2(x.x, x.y, h0, l0);
        split2(x.z, x.w, h1, l1);
        hi[i] = make_uint2(h0, h1);
        lo[i] = make_uint2(l0, l1);
    }
}

// ---------------------------------------------------------------------------
// shared mma mainloop: 128x128 fp32 tile in d[2][8][4] (3-term hi/lo)
// 4-stage cp.async ring, 3-stage lookahead, 1 barrier/iter, 32 iters (KC=16).
// ---------------------------------------------------------------------------
struct MmaCtx {
    float d[2][8][4];
    uint32_t aHi[2], aLo[2], bHi[4], bLo[4];
};

__device__ __forceinline__ void mma_mainloop(
    MmaCtx& cx, uint32_t sb,
    const __nv_bfloat16* srcAh, const __nv_bfloat16* srcAl,
    const __nv_bfloat16* srcBh, const __nv_bfloat16* srcBl)
{
    const int tid = threadIdx.x;
    const int wid = tid >> 5, lane = tid & 31;
    const int wm = (wid & 3) * 32, wn = (wid >> 2) * 64;

    #pragma unroll
    for (int mb = 0; mb < 2; mb++) {
        uint32_t ro = (uint32_t)(wm + mb * 16 + (lane & 15)) * ROW_B + (lane >> 4) * 16;
        cx.aHi[mb] = sb + ro;
        cx.aLo[mb] = sb + ARR_B + ro;
    }
    #pragma unroll
    for (int p = 0; p < 4; p++) {
        uint32_t ro = (uint32_t)(wn + p * 16 + (lane >> 4) * 8 + (lane & 7)) * ROW_B
                    + ((lane >> 3) & 1) * 16;
        cx.bHi[p] = sb + 2 * ARR_B + ro;
        cx.bLo[p] = sb + 3 * ARR_B + ro;
    }
    #pragma unroll
    for (int mb = 0; mb < 2; mb++)
        #pragma unroll
        for (int nb = 0; nb < 8; nb++)
            #pragma unroll
            for (int e = 0; e < 4; e++) cx.d[mb][nb][e] = 0.f;

    // per-thread loader coords: 1 chunk per array per stage
    const int lr = tid >> 1;           // row 0..127
    const int lc = tid & 1;            // 16B half of the 32B row
    const uint32_t ldst = (uint32_t)(lr * ROW_B + lc * 16);
    const size_t lgo = (size_t)lr * DD + lc * 8;

    auto load_stage = [&](int st, int k0) {
        uint32_t stb = sb + (uint32_t)st * STAGE_B + ldst;
        cpasync16(stb,             srcAh + lgo + k0);
        cpasync16(stb + ARR_B,     srcAl + lgo + k0);
        cpasync16(stb + 2 * ARR_B, srcBh + lgo + k0);
        cpasync16(stb + 3 * ARR_B, srcBl + lgo + k0);
        CP_COMMIT();
    };

    load_stage(0, 0);
    load_stage(1, 16);
    load_stage(2, 32);

    for (int it = 0; it < 32; it++) {
        if (it + 2 < 32)      { CP_WAIT(2); }
        else if (it + 1 < 32) { CP_WAIT(1); }
        else                  { CP_WAIT(0); }
        __syncthreads();      // stage `it` visible to all; all done with it-1
        if (it + 3 < 32) load_stage((it + 3) & 3, (it + 3) * 16);

        const uint32_t so = (uint32_t)(it & 3) * STAGE_B;
        unsigned ah[2][4], al[2][4];
        #pragma unroll
        for (int mb = 0; mb < 2; mb++) {
            ldsm4(ah[mb], cx.aHi[mb] + so);
            ldsm4(al[mb], cx.aLo[mb] + so);
        }
        #pragma unroll
        for (int p = 0; p < 4; p++) {
            unsigned tbh[4], tbl[4];
            ldsm4(tbh, cx.bHi[p] + so);
            ldsm4(tbl, cx.bLo[p] + so);
            // term-major: 4 independent accumulators between reuses
            #pragma unroll
            for (int mb = 0; mb < 2; mb++)
                #pragma unroll
                for (int qn = 0; qn < 2; qn++)
                    mma16816(cx.d[mb][2 * p + qn], ah[mb], &tbh[2 * qn]);
            #pragma unroll
            for (int mb = 0; mb < 2; mb++)
                #pragma unroll
                for (int qn = 0; qn < 2; qn++)
                    mma16816(cx.d[mb][2 * p + qn], ah[mb], &tbl[2 * qn]);
            #pragma unroll
            for (int mb = 0; mb < 2; mb++)
                #pragma unroll
                for (int qn = 0; qn < 2; qn++)
                    mma16816(cx.d[mb][2 * p + qn], al[mb], &tbh[2 * qn]);
        }
    }
}

// ---------------------------------------------------------------------------
// projection + L2 norm -> bf16 outputs in [bh][s][k]
// __launch_bounds__(256, 2): cap regs at 128 so 2 CTAs/SM fit (regfile 64K).
// ---------------------------------------------------------------------------
__global__ __launch_bounds__(256, 2) void proj_mma()
{
    extern __shared__ __align__(16) char dsm[];
    const uint32_t sb = smem_u32(dsm);

    const int n0 = blockIdx.x * 128;
    const int m0 = blockIdx.y * 128;
    const int t  = n0 >> 9;
    const int nr = n0 & 511;

    const __nv_bfloat16* srcAh = g_ih + (size_t)t * (SS * BB * DD) + (size_t)m0 * DD;
    const __nv_bfloat16* srcAl = g_il + (size_t)t * (SS * BB * DD) + (size_t)m0 * DD;
    const __nv_bfloat16* srcBh = g_wh + (size_t)t * (DD * DD) + (size_t)nr * DD;
    const __nv_bfloat16* srcBl = g_wl + (size_t)t * (DD * DD) + (size_t)nr * DD;

    __nv_bfloat16* dsth = (t == 0) ? g_qh : (t == 1) ? g_kh : g_vh;
    __nv_bfloat16* dstl = g_vl;
    const bool write_lo = (t == 2);     // only V needs the lo residue

    MmaCtx cx;
    mma_mainloop(cx, sb, srcAh, srcAl, srcBh, srcBl);

    const int tid = threadIdx.x;
    const int wid = tid >> 5, lane = tid & 31;
    const int wm = (wid & 3) * 32, wn = (wid >> 2) * 64;
    const int r0 = lane >> 2, c0 = lane & 3;
    const int h = (nr >> 6) + (wn >> 6);

    #pragma unroll
    for (int mb = 0; mb < 2; mb++) {
        float ssa = 0.f, ssb = 0.f;
        #pragma unroll
        for (int nb = 0; nb < 8; nb++) {
            float* d = cx.d[mb][nb];
            ssa = fmaf(d[0], d[0], fmaf(d[1], d[1], ssa));
            ssb = fmaf(d[2], d[2], fmaf(d[3], d[3], ssb));
        }
        ssa += __shfl_xor_sync(0xffffffffu, ssa, 1);
        ssa += __shfl_xor_sync(0xffffffffu, ssa, 2);
        ssb += __shfl_xor_sync(0xffffffffu, ssb, 1);
        ssb += __shfl_xor_sync(0xffffffffu, ssb, 2);
        float inva = 1.0f / fmaxf(sqrtf(ssa), 1e-12f);
        float invb = 1.0f / fmaxf(sqrtf(ssb), 1e-12f);

        int ma = m0 + wm + mb * 16 + r0;
        int mb2 = ma + 8;
        int ba = ma & 15, sa = ma >> 4;
        int bbb = mb2 & 15, sbb = mb2 >> 4;
        size_t rowA = (((size_t)(ba * HH + h)) * SS + sa) * KK;
        size_t rowB = (((size_t)(bbb * HH + h)) * SS + sbb) * KK;
        #pragma unroll
        for (int nb = 0; nb < 8; nb++) {
            int kk = ((wn & 63) + nb * 8 + 2 * c0);
            float* d = cx.d[mb][nb];
            unsigned hA, lA, hB, lB;
            split2(d[0] * inva, d[1] * inva, hA, lA);
            split2(d[2] * invb, d[3] * invb, hB, lB);
            *(unsigned*)&dsth[rowA + kk] = hA;
            *(unsigned*)&dsth[rowB + kk] = hB;
            if (write_lo) {
                *(unsigned*)&dstl[rowA + kk] = lA;
                *(unsigned*)&dstl[rowB + kk] = lB;
            }
        }
    }
}

// ---------------------------------------------------------------------------
// output projection: out[m][n] fp32
// ---------------------------------------------------------------------------
__global__ __launch_bounds__(256, 2) void outproj_mma(float* __restrict__ out)
{
    extern __shared__ __align__(16) char dsm[];
    const uint32_t sb = smem_u32(dsm);

    const int n0 = blockIdx.x * 128;
    const int m0 = blockIdx.y * 128;

    MmaCtx cx;
    mma_mainloop(cx, sb, g_ath + (size_t)m0 * DD, g_atl + (size_t)m0 * DD,
                 g_oh + (size_t)n0 * DD, g_ol + (size_t)n0 * DD);

    const int tid = threadIdx.x;
    const int wid = tid >> 5, lane = tid & 31;
    const int wm = (wid & 3) * 32, wn = (wid >> 2) * 64;
    const int r0 = lane >> 2, c0 = lane & 3;

    #pragma unroll
    for (int mb = 0; mb < 2; mb++) {
        int ma = m0 + wm + mb * 16 + r0;
        float* pa = out + (size_t)ma * DD;
        float* pb = out + (size_t)(ma + 8) * DD;
        #pragma unroll
        for (int nb = 0; nb < 8; nb++) {
            int n = n0 + wn + nb * 8 + 2 * c0;
            float* d = cx.d[mb][nb];
            *(float2*)&pa[n] = make_float2(d[0], d[1]);
            *(float2*)&pb[n] = make_float2(d[2], d[3]);
        }
    }
}

// ---------------------------------------------------------------------------
// attention via mma.sync: 128 q-rows per CTA, 8 warps x 16 rows, t-chunks 64.
// scores = Qh·Kh; P = exp(s/8) hi+lo; O += Ph·(Vh+Vl) + Pl·Vh.
// 3-stage cp.async ring (kh,vh,vl per stage), single sync per chunk.
// ---------------------------------------------------------------------------
#define AT_ROW   144
#define AT_ARR   (64 * AT_ROW)        // 9216
#define AT_STAGE (3 * AT_ARR)         // 27648
#define AT_QOFF  (3 * AT_STAGE)       // 82944
#define ATT_SMEM (AT_QOFF + 128 * AT_ROW)   // 101376

__global__ __launch_bounds__(256, 2) void attn_mma()
{
    extern __shared__ __align__(16) char dsm[];
    const uint32_t sb = smem_u32(dsm);

    const int tid = threadIdx.x, wid = tid >> 5, lane = tid & 31;
    const int s0 = blockIdx.x * 128;
    const int bh = blockIdx.y;
    const int b = bh >> 3, h = bh & 7;

    const __nv_bfloat16* qh = g_qh + (size_t)bh * SS * KK + (size_t)s0 * KK;
    const __nv_bfloat16* kh = g_kh + (size_t)bh * SS * KK;
    const __nv_bfloat16* vh = g_vh + (size_t)bh * SS * KK;
    const __nv_bfloat16* vl = g_vl + (size_t)bh * SS * KK;

    // chunk loader: kh,vh,vl tiles of 64 rows x 64 bf16 (6 chunks/thread)
    auto load_chunk = [&](uint32_t stb, int t0) {
        #pragma unroll
        for (int i = 0; i < 6; i++) {
            int idx = tid + i * 256;
            int a = idx >> 9, ci = idx & 511, r = ci >> 3, c = ci & 7;
            const __nv_bfloat16* s = (a == 0) ? kh : (a == 1) ? vh : vl;
            cpasync16(stb + a * AT_ARR + (uint32_t)(r * AT_ROW + c * 16),
                      s + (size_t)(t0 + r) * KK + c * 8);
        }
    };

    // group 0: Q tile (hi only), 128 rows x 64 bf16
    #pragma unroll
    for (int i = 0; i < 4; i++) {
        int idx = tid + i * 256;
        int r = idx >> 3, c = idx & 7;
        cpasync16(sb + AT_QOFF + (uint32_t)(r * AT_ROW + c * 16),
                  qh + (size_t)r * KK + c * 8);
    }
    CP_COMMIT();
    // groups 1,2: chunks 0,1
    load_chunk(sb, 0); CP_COMMIT();
    load_chunk(sb + AT_STAGE, 64); CP_COMMIT();

    CP_WAIT(2);          // Q ready
    __syncthreads();
    unsigned qf[4][4];
    const int wq0 = wid * 16;
    #pragma unroll
    for (int ks = 0; ks < 4; ks++)
        ldsm4(qf[ks], sb + AT_QOFF + (uint32_t)((wq0 + (lane & 15)) * AT_ROW)
                        + ks * 32 + (lane >> 4) * 16);

    float o[8][4] = {};
    float l0 = 0.f, l1 = 0.f;

    for (int c = 0; c < 16; c++) {
        if (c < 15) { CP_WAIT(1); } else { CP_WAIT(0); }
        __syncthreads();                 // all warps done with stage (c+2)%3's prior use
        if (c + 2 < 16) {
            load_chunk(sb + (uint32_t)((c + 2) % 3) * AT_STAGE, (c + 2) * 64);
            CP_COMMIT();
        }
        const uint32_t so = sb + (uint32_t)(c % 3) * AT_STAGE;

        // scores: Qh . Kh — p-pairs: 4 independent accumulators in flight
        float sc[8][4] = {};
        #pragma unroll
        for (int ks = 0; ks < 4; ks++) {
            #pragma unroll
            for (int pp = 0; pp < 2; pp++) {
                unsigned kh4a[4], kh4b[4];
                uint32_t roa = (uint32_t)(((2 * pp) * 16 + (lane >> 4) * 8 + (lane & 7)) * AT_ROW)
                             + ks * 32 + ((lane >> 3) & 1) * 16;
                uint32_t rob = roa + 16 * AT_ROW;
                ldsm4(kh4a, so + roa);
                ldsm4(kh4b, so + rob);
                mma16816(sc[4 * pp + 0], qf[ks], &kh4a[0]);
                mma16816(sc[4 * pp + 1], qf[ks], &kh4a[2]);
                mma16816(sc[4 * pp + 2], qf[ks], &kh4b[0]);
                mma16816(sc[4 * pp + 3], qf[ks], &kh4b[2]);
            }
        }

        // exp (bounded scores -> no running max), row sums
        float ev[8][4];
        #pragma unroll
        for (int nt = 0; nt < 8; nt++) {
            ev[nt][0] = __expf(sc[nt][0] * 0.125f);
            ev[nt][1] = __expf(sc[nt][1] * 0.125f);
            ev[nt][2] = __expf(sc[nt][2] * 0.125f);
            ev[nt][3] = __expf(sc[nt][3] * 0.125f);
            l0 += ev[nt][0] + ev[nt][1];
            l1 += ev[nt][2] + ev[nt][3];
        }

        // O += Ph·(Vh+Vl) + Pl·Vh — p-pairs, term-major (4 indep accs per term)
        #pragma unroll
        for (int ts = 0; ts < 4; ts++) {
            unsigned ph[4], pl[4];
            split2(ev[2 * ts][0],     ev[2 * ts][1],     ph[0], pl[0]);
            split2(ev[2 * ts][2],     ev[2 * ts][3],     ph[1], pl[1]);
            split2(ev[2 * ts + 1][0], ev[2 * ts + 1][1], ph[2], pl[2]);
            split2(ev[2 * ts + 1][2], ev[2 * ts + 1][3], ph[3], pl[3]);
            #pragma unroll
            for (int pp = 0; pp < 2; pp++) {
                uint32_t roa = (uint32_t)((ts * 16 + ((lane >> 3) & 1) * 8 + (lane & 7)) * AT_ROW)
                             + ((2 * pp) * 16 + (lane >> 4) * 8) * 2;
                uint32_t rob = roa + 32;
                unsigned vh4a[4], vl4a[4], vh4b[4], vl4b[4];
                ldsm4t(vh4a, so + 1 * AT_ARR + roa);
                ldsm4t(vl4a, so + 2 * AT_ARR + roa);
                ldsm4t(vh4b, so + 1 * AT_ARR + rob);
                ldsm4t(vl4b, so + 2 * AT_ARR + rob);
                // term 1: Ph . Vh
                mma16816(o[4 * pp + 0], ph, &vh4a[0]);
                mma16816(o[4 * pp + 1], ph, &vh4a[2]);
                mma16816(o[4 * pp + 2], ph, &vh4b[0]);
                mma16816(o[4 * pp + 3], ph, &vh4b[2]);
                // term 2: Ph . Vl
                mma16816(o[4 * pp + 0], ph, &vl4a[0]);
                mma16816(o[4 * pp + 1], ph, &vl4a[2]);
                mma16816(o[4 * pp + 2], ph, &vl4b[0]);
                mma16816(o[4 * pp + 3], ph, &vl4b[2]);
                // term 3: Pl . Vh
                mma16816(o[4 * pp + 0], pl, &vh4a[0]);
                mma16816(o[4 * pp + 1], pl, &vh4a[2]);
                mma16816(o[4 * pp + 2], pl, &vh4b[0]);
                mma16816(o[4 * pp + 3], pl, &vh4b[2]);
            }
        }
    }

    // softmax denominators: reduce col-pairs across the quad
    l0 += __shfl_xor_sync(0xffffffffu, l0, 1);
    l0 += __shfl_xor_sync(0xffffffffu, l0, 2);
    l1 += __shfl_xor_sync(0xffffffffu, l1, 1);
    l1 += __shfl_xor_sync(0xffffffffu, l1, 2);
    float inv0 = 1.0f / l0, inv1 = 1.0f / l1;

    const int r0 = lane >> 2, c0 = lane & 3;
    int sA = s0 + wq0 + r0;
    size_t mA = ((size_t)sA * BB + b) * (HH * KK);
    size_t mB = ((size_t)(sA + 8) * BB + b) * (HH * KK);
    #pragma unroll
    for (int nk = 0; nk < 8; nk++) {
        int j = h * KK + nk * 8 + 2 * c0;
        unsigned h0, lo0, h1, lo1;
        split2(o[nk][0] * inv0, o[nk][1] * inv0, h0, lo0);
        split2(o[nk][2] * inv1, o[nk][3] * inv1, h1, lo1);
        *(unsigned*)&g_ath[mA + j] = h0;
        *(unsigned*)&g_atl[mA + j] = lo0;
        *(unsigned*)&g_ath[mB + j] = h1;
        *(unsigned*)&g_atl[mB + j] = lo1;
    }
}

// ---------------------------------------------------------------------------
extern "C" void kernel_launch(void* const* d_in, const int* in_sizes, int n_in,
                              void* d_out, int out_size)
{
    const float* q    = (const float*)d_in[0];
    const float* k    = (const float*)d_in[1];
    const float* v    = (const float*)d_in[2];
    const float* WQ   = (const float*)d_in[3];
    const float* WK   = (const float*)d_in[4];
    const float* WV   = (const float*)d_in[5];
    const float* Wout = (const float*)d_in[6];
    float* out = (float*)d_out;

    cudaFuncSetAttribute(proj_mma,
                         cudaFuncAttributeMaxDynamicSharedMemorySize, MMA_SMEM);
    cudaFuncSetAttribute(outproj_mma,
                         cudaFuncAttributeMaxDynamicSharedMemorySize, MMA_SMEM);
    cudaFuncSetAttribute(attn_mma,
                         cudaFuncAttributeMaxDynamicSharedMemorySize, ATT_SMEM);

    cvt_all<<<dim3(1024, 1, 7), 256>>>((const float4*)q, (const float4*)k,
                                       (const float4*)v, (const float4*)WQ,
                                       (const float4*)WK, (const float4*)WV,
                                       (const float4*)Wout);
    proj_mma<<<dim3(12, 128), 256, MMA_SMEM>>>();
    attn_mma<<<dim3(SS / 128, BB * HH), 256, ATT_SMEM>>>();
    outproj_mma<<<dim3(4, 128), 256, MMA_SMEM>>>(out);
}

// round 15
// speedup vs baseline: 1.4038x; 1.2782x over previous
#include <cuda_runtime.h>
#include <cuda_bf16.h>
#include <math.h>
#include <stdint.h>

#define SS 1024
#define BB 16
#define DD 512
#define HH 8
#define KK 64

using ull = unsigned long long;

// bf16 hi/lo splits of inputs & weights (for proj / outproj GEMMs)
__device__ __nv_bfloat16 g_ih[3 * SS * BB * DD];   // q,k,v inputs [t][m=s*16+b][d]
__device__ __nv_bfloat16 g_il[3 * SS * BB * DD];   // lo used only for v (t=2)
__device__ __nv_bfloat16 g_wh[3 * DD * DD];        // WQ,WK,WV [t][n][d]
__device__ __nv_bfloat16 g_wl[3 * DD * DD];        // lo used only for WV
__device__ __nv_bfloat16 g_oh[DD * DD];            // Wout [n][j]
__device__ __nv_bfloat16 g_ol[DD * DD];
// normalized projections, bf16, [bh][s][k]  (K hi only; V hi+lo)
__device__ __nv_bfloat16 g_qh[BB * HH * SS * KK];
__device__ __nv_bfloat16 g_kh[BB * HH * SS * KK];
__device__ __nv_bfloat16 g_vh[BB * HH * SS * KK];
__device__ __nv_bfloat16 g_vl[BB * HH * SS * KK];
// attention output [m = s*16+b][j = h*64+k], bf16 hi/lo
__device__ __nv_bfloat16 g_ath[SS * BB * HH * KK];
__device__ __nv_bfloat16 g_atl[SS * BB * HH * KK];

// ---------------------------------------------------------------------------
// helpers
// ---------------------------------------------------------------------------
__device__ __forceinline__ uint32_t smem_u32(const void* p) {
    uint32_t a;
    asm("{ .reg .u64 t; cvta.to.shared.u64 t, %1; cvt.u32.u64 %0, t; }"
        : "=r"(a) : "l"(p));
    return a;
}

__device__ __forceinline__ unsigned bpack(float lo_elem, float hi_elem) {
    unsigned r;  // lower 16 = bf16(lo_elem), upper 16 = bf16(hi_elem)
    asm("cvt.rn.bf16x2.f32 %0, %1, %2;" : "=r"(r) : "f"(hi_elem), "f"(lo_elem));
    return r;
}
__device__ __forceinline__ void split2(float x, float y, unsigned& hi, unsigned& lo) {
    unsigned h = bpack(x, y);
    float hx = __uint_as_float(h << 16);
    float hy = __uint_as_float(h & 0xffff0000u);
    hi = h;
    lo = bpack(x - hx, y - hy);
}

__device__ __forceinline__ void ldsm4(unsigned* r, uint32_t addr) {
    asm volatile("ldmatrix.sync.aligned.m8n8.x4.shared.b16 {%0,%1,%2,%3}, [%4];"
                 : "=r"(r[0]), "=r"(r[1]), "=r"(r[2]), "=r"(r[3]) : "r"(addr));
}
__device__ __forceinline__ void ldsm4t(unsigned* r, uint32_t addr) {
    asm volatile("ldmatrix.sync.aligned.m8n8.x4.trans.shared.b16 {%0,%1,%2,%3}, [%4];"
                 : "=r"(r[0]), "=r"(r[1]), "=r"(r[2]), "=r"(r[3]) : "r"(addr));
}
// non-volatile: pure register computation, lets ptxas interleave MMAs.
__device__ __forceinline__ void mma16816(float* d, const unsigned* a, const unsigned* b) {
    asm("mma.sync.aligned.m16n8k16.row.col.f32.bf16.bf16.f32 "
        "{%0,%1,%2,%3}, {%4,%5,%6,%7}, {%8,%9}, {%0,%1,%2,%3};"
        : "+f"(d[0]), "+f"(d[1]), "+f"(d[2]), "+f"(d[3])
        : "r"(a[0]), "r"(a[1]), "r"(a[2]), "r"(a[3]), "r"(b[0]), "r"(b[1]));
}
__device__ __forceinline__ void cpasync16(uint32_t saddr, const void* gaddr) {
    asm volatile("cp.async.ca.shared.global [%0], [%1], 16;"
                 :: "r"(saddr), "l"(gaddr) : "memory");
}
#define CP_COMMIT() asm volatile("cp.async.commit_group;" ::: "memory")
#define CP_WAIT(n)  asm volatile("cp.async.wait_group %0;" :: "n"(n) : "memory")

// GEMM smem layout (R11-proven): rows of 32 bf16 padded to 80B, 2 stages, KC=32
#define ROW_B   80
#define ARR_B   10240
#define B_HI    20480
#define B_LO    30720
#define STAGE_B 40960
#define MMA_SMEM (2 * STAGE_B)

// ---------------------------------------------------------------------------
// fused convert: fp32 -> bf16 hi/lo, one launch, z selects array.
// lo residues are skipped where never read (q,k inputs; WQ,WK).
// ---------------------------------------------------------------------------
__global__ void cvt_all(const float4* __restrict__ q, const float4* __restrict__ k,
                        const float4* __restrict__ v, const float4* __restrict__ wq,
                        const float4* __restrict__ wk, const float4* __restrict__ wv,
                        const float4* __restrict__ wo)
{
    const int NIN = SS * BB * DD / 4, NW = DD * DD / 4;
    const int z = blockIdx.z;
    const float4* src;
    uint2 *hi, *lo;
    int n4;
    bool wlo = true;
    switch (z) {
        case 0: src = q;  hi = (uint2*)g_ih;           lo = (uint2*)g_il;           n4 = NIN; wlo = false; break;
        case 1: src = k;  hi = (uint2*)g_ih + NIN;     lo = (uint2*)g_il + NIN;     n4 = NIN; wlo = false; break;
        case 2: src = v;  hi = (uint2*)g_ih + 2 * NIN; lo = (uint2*)g_il + 2 * NIN; n4 = NIN; break;
        case 3: src = wq; hi = (uint2*)g_wh;           lo = (uint2*)g_wl;           n4 = NW;  wlo = false; break;
        case 4: src = wk; hi = (uint2*)g_wh + NW;      lo = (uint2*)g_wl + NW;      n4 = NW;  wlo = false; break;
        case 5: src = wv; hi = (uint2*)g_wh + 2 * NW;  lo = (uint2*)g_wl + 2 * NW;  n4 = NW;  break;
        default: src = wo; hi = (uint2*)g_oh;          lo = (uint2*)g_ol;           n4 = NW;  break;
    }
    for (int i = blockIdx.x * blockDim.x + threadIdx.x; i < n4;
         i += gridDim.x * blockDim.x) {
        float4 x = src[i];
        unsigned h0, l0, h1, l1;
        split2(x.x, x.y, h0, l0);
        split2(x.z, x.w, h1, l1);
        hi[i] = make_uint2(h0, h1);
        if (wlo) lo[i] = make_uint2(l0, l1);
    }
}

// ---------------------------------------------------------------------------
// shared mma mainloop (R11 2-stage KC=32), templated on term count.
// NT=3: d += Ah·Bh + Ah·Bl + Al·Bh.   NT=1: d += Ah·Bh (half the loads too).
// ---------------------------------------------------------------------------
struct MmaCtx {
    float d[2][8][4];
    uint32_t aHi[2], aLo[2], bHi[4], bLo[4];
};

template <int NT>
__device__ __forceinline__ void mma_mainloop(
    MmaCtx& cx, uint32_t sb,
    const __nv_bfloat16* srcAh, const __nv_bfloat16* srcAl,
    const __nv_bfloat16* srcBh, const __nv_bfloat16* srcBl)
{
    const int tid = threadIdx.x;
    const int wid = tid >> 5, lane = tid & 31;
    const int wm = (wid & 3) * 32, wn = (wid >> 2) * 64;

    #pragma unroll
    for (int mb = 0; mb < 2; mb++) {
        uint32_t ro = (uint32_t)(wm + mb * 16 + (lane & 15)) * ROW_B + (lane >> 4) * 16;
        cx.aHi[mb] = sb + ro;
        cx.aLo[mb] = sb + ARR_B + ro;
    }
    #pragma unroll
    for (int p = 0; p < 4; p++) {
        uint32_t ro = (uint32_t)(wn + p * 16 + (lane >> 4) * 8 + (lane & 7)) * ROW_B
                    + ((lane >> 3) & 1) * 16;
        cx.bHi[p] = sb + B_HI + ro;
        cx.bLo[p] = sb + B_LO + ro;
    }
    #pragma unroll
    for (int mb = 0; mb < 2; mb++)
        #pragma unroll
        for (int nb = 0; nb < 8; nb++)
            #pragma unroll
            for (int e = 0; e < 4; e++) cx.d[mb][nb][e] = 0.f;

    // loader: NT=3 -> 4 arrays (Ah,Al,Bh,Bl); NT=1 -> 2 arrays (Ah,Bh)
    constexpr int NCH = (NT == 3) ? 8 : 4;
    auto load_stage = [&](uint32_t stb, int k0) {
        #pragma unroll
        for (int i = 0; i < NCH; i++) {
            int idx = tid + i * 256;
            int a = idx >> 9, ci = idx & 511, r = ci >> 2, cc = ci & 3;
            const __nv_bfloat16* s;
            uint32_t aoff;
            if (NT == 3) {
                s = (a == 0) ? srcAh : (a == 1) ? srcAl : (a == 2) ? srcBh : srcBl;
                aoff = (uint32_t)a * ARR_B;
            } else {
                s = (a == 0) ? srcAh : srcBh;
                aoff = (a == 0) ? 0u : (uint32_t)B_HI;
            }
            cpasync16(stb + aoff + (uint32_t)(r * ROW_B + cc * 16),
                      s + (size_t)r * DD + k0 + cc * 8);
        }
        CP_COMMIT();
    };

    load_stage(sb, 0);

    for (int it = 0; it < 16; it++) {
        if (it + 1 < 16) {
            load_stage(sb + (uint32_t)((it + 1) & 1) * STAGE_B, (it + 1) * 32);
            CP_WAIT(1);
        } else {
            CP_WAIT(0);
        }
        __syncthreads();

        const uint32_t so = (uint32_t)(it & 1) * STAGE_B;
        #pragma unroll
        for (int ks = 0; ks < 2; ks++) {
            const uint32_t off = so + ks * 32;
            unsigned ah[2][4], al[2][4];
            #pragma unroll
            for (int mb = 0; mb < 2; mb++) {
                ldsm4(ah[mb], cx.aHi[mb] + off);
                if (NT == 3) ldsm4(al[mb], cx.aLo[mb] + off);
            }
            #pragma unroll
            for (int p = 0; p < 4; p++) {
                unsigned tbh[4], tbl[4];
                ldsm4(tbh, cx.bHi[p] + off);
                if (NT == 3) ldsm4(tbl, cx.bLo[p] + off);
                #pragma unroll
                for (int mb = 0; mb < 2; mb++)
                    #pragma unroll
                    for (int qn = 0; qn < 2; qn++)
                        mma16816(cx.d[mb][2 * p + qn], ah[mb], &tbh[2 * qn]);
                if (NT == 3) {
                    #pragma unroll
                    for (int mb = 0; mb < 2; mb++)
                        #pragma unroll
                        for (int qn = 0; qn < 2; qn++)
                            mma16816(cx.d[mb][2 * p + qn], ah[mb], &tbl[2 * qn]);
                    #pragma unroll
                    for (int mb = 0; mb < 2; mb++)
                        #pragma unroll
                        for (int qn = 0; qn < 2; qn++)
                            mma16816(cx.d[mb][2 * p + qn], al[mb], &tbh[2 * qn]);
                }
            }
        }
        __syncthreads();
    }
}

// ---------------------------------------------------------------------------
// projection + L2 norm -> bf16 outputs in [bh][s][k]
// Q,K: 1-term GEMM (hi-only path feeds scores; error enters attenuated).
// V:   3-term GEMM (passes linearly to output).
// ---------------------------------------------------------------------------
__global__ __launch_bounds__(256) void proj_mma()
{
    extern __shared__ __align__(16) char dsm[];
    const uint32_t sb = smem_u32(dsm);

    const int n0 = blockIdx.x * 128;
    const int m0 = blockIdx.y * 128;
    const int t  = n0 >> 9;
    const int nr = n0 & 511;

    const __nv_bfloat16* srcAh = g_ih + (size_t)t * (SS * BB * DD) + (size_t)m0 * DD;
    const __nv_bfloat16* srcAl = g_il + (size_t)t * (SS * BB * DD) + (size_t)m0 * DD;
    const __nv_bfloat16* srcBh = g_wh + (size_t)t * (DD * DD) + (size_t)nr * DD;
    const __nv_bfloat16* srcBl = g_wl + (size_t)t * (DD * DD) + (size_t)nr * DD;

    __nv_bfloat16* dsth = (t == 0) ? g_qh : (t == 1) ? g_kh : g_vh;
    __nv_bfloat16* dstl = g_vl;
    const bool write_lo = (t == 2);     // only V needs the lo residue

    MmaCtx cx;
    if (t == 2) mma_mainloop<3>(cx, sb, srcAh, srcAl, srcBh, srcBl);
    else        mma_mainloop<1>(cx, sb, srcAh, srcAl, srcBh, srcBl);

    const int tid = threadIdx.x;
    const int wid = tid >> 5, lane = tid & 31;
    const int wm = (wid & 3) * 32, wn = (wid >> 2) * 64;
    const int r0 = lane >> 2, c0 = lane & 3;
    const int h = (nr >> 6) + (wn >> 6);

    #pragma unroll
    for (int mb = 0; mb < 2; mb++) {
        float ssa = 0.f, ssb = 0.f;
        #pragma unroll
        for (int nb = 0; nb < 8; nb++) {
            float* d = cx.d[mb][nb];
            ssa = fmaf(d[0], d[0], fmaf(d[1], d[1], ssa));
            ssb = fmaf(d[2], d[2], fmaf(d[3], d[3], ssb));
        }
        ssa += __shfl_xor_sync(0xffffffffu, ssa, 1);
        ssa += __shfl_xor_sync(0xffffffffu, ssa, 2);
        ssb += __shfl_xor_sync(0xffffffffu, ssb, 1);
        ssb += __shfl_xor_sync(0xffffffffu, ssb, 2);
        float inva = 1.0f / fmaxf(sqrtf(ssa), 1e-12f);
        float invb = 1.0f / fmaxf(sqrtf(ssb), 1e-12f);

        int ma = m0 + wm + mb * 16 + r0;
        int mb2 = ma + 8;
        int ba = ma & 15, sa = ma >> 4;
        int bbb = mb2 & 15, sbb = mb2 >> 4;
        size_t rowA = (((size_t)(ba * HH + h)) * SS + sa) * KK;
        size_t rowB = (((size_t)(bbb * HH + h)) * SS + sbb) * KK;
        #pragma unroll
        for (int nb = 0; nb < 8; nb++) {
            int kk = ((wn & 63) + nb * 8 + 2 * c0);
            float* d = cx.d[mb][nb];
            unsigned hA, lA, hB, lB;
            split2(d[0] * inva, d[1] * inva, hA, lA);
            split2(d[2] * invb, d[3] * invb, hB, lB);
            *(unsigned*)&dsth[rowA + kk] = hA;
            *(unsigned*)&dsth[rowB + kk] = hB;
            if (write_lo) {
                *(unsigned*)&dstl[rowA + kk] = lA;
                *(unsigned*)&dstl[rowB + kk] = lB;
            }
        }
    }
}

// ---------------------------------------------------------------------------
// output projection: out[m][n] fp32 (3-term)
// ---------------------------------------------------------------------------
__global__ __launch_bounds__(256) void outproj_mma(float* __restrict__ out)
{
    extern __shared__ __align__(16) char dsm[];
    const uint32_t sb = smem_u32(dsm);

    const int n0 = blockIdx.x * 128;
    const int m0 = blockIdx.y * 128;

    MmaCtx cx;
    mma_mainloop<3>(cx, sb, g_ath + (size_t)m0 * DD, g_atl + (size_t)m0 * DD,
                    g_oh + (size_t)n0 * DD, g_ol + (size_t)n0 * DD);

    const int tid = threadIdx.x;
    const int wid = tid >> 5, lane = tid & 31;
    const int wm = (wid & 3) * 32, wn = (wid >> 2) * 64;
    const int r0 = lane >> 2, c0 = lane & 3;

    #pragma unroll
    for (int mb = 0; mb < 2; mb++) {
        int ma = m0 + wm + mb * 16 + r0;
        float* pa = out + (size_t)ma * DD;
        float* pb = out + (size_t)(ma + 8) * DD;
        #pragma unroll
        for (int nb = 0; nb < 8; nb++) {
            int n = n0 + wn + nb * 8 + 2 * c0;
            float* d = cx.d[mb][nb];
            *(float2*)&pa[n] = make_float2(d[0], d[1]);
            *(float2*)&pb[n] = make_float2(d[2], d[3]);
        }
    }
}

// ---------------------------------------------------------------------------
// attention via mma.sync: 128 q-rows per CTA, 8 warps x 16 rows, t-chunks 64.
// scores = Qh·Kh; P = exp(s/8) hi+lo; O += Ph·(Vh+Vl) + Pl·Vh.
// 3-stage cp.async ring (kh,vh,vl per stage), single sync per chunk.
// ---------------------------------------------------------------------------
#define AT_ROW   144
#define AT_ARR   (64 * AT_ROW)        // 9216
#define AT_STAGE (3 * AT_ARR)         // 27648
#define AT_QOFF  (3 * AT_STAGE)       // 82944
#define ATT_SMEM (AT_QOFF + 128 * AT_ROW)   // 101376

__global__ __launch_bounds__(256, 2) void attn_mma()
{
    extern __shared__ __align__(16) char dsm[];
    const uint32_t sb = smem_u32(dsm);

    const int tid = threadIdx.x, wid = tid >> 5, lane = tid & 31;
    const int s0 = blockIdx.x * 128;
    const int bh = blockIdx.y;
    const int b = bh >> 3, h = bh & 7;

    const __nv_bfloat16* qh = g_qh + (size_t)bh * SS * KK + (size_t)s0 * KK;
    const __nv_bfloat16* kh = g_kh + (size_t)bh * SS * KK;
    const __nv_bfloat16* vh = g_vh + (size_t)bh * SS * KK;
    const __nv_bfloat16* vl = g_vl + (size_t)bh * SS * KK;

    // chunk loader: kh,vh,vl tiles of 64 rows x 64 bf16 (6 chunks/thread)
    auto load_chunk = [&](uint32_t stb, int t0) {
        #pragma unroll
        for (int i = 0; i < 6; i++) {
            int idx = tid + i * 256;
            int a = idx >> 9, ci = idx & 511, r = ci >> 3, c = ci & 7;
            const __nv_bfloat16* s = (a == 0) ? kh : (a == 1) ? vh : vl;
            cpasync16(stb + a * AT_ARR + (uint32_t)(r * AT_ROW + c * 16),
                      s + (size_t)(t0 + r) * KK + c * 8);
        }
    };

    // group 0: Q tile (hi only), 128 rows x 64 bf16
    #pragma unroll
    for (int i = 0; i < 4; i++) {
        int idx = tid + i * 256;
        int r = idx >> 3, c = idx & 7;
        cpasync16(sb + AT_QOFF + (uint32_t)(r * AT_ROW + c * 16),
                  qh + (size_t)r * KK + c * 8);
    }
    CP_COMMIT();
    // groups 1,2: chunks 0,1
    load_chunk(sb, 0); CP_COMMIT();
    load_chunk(sb + AT_STAGE, 64); CP_COMMIT();

    CP_WAIT(2);          // Q ready
    __syncthreads();
    unsigned qf[4][4];
    const int wq0 = wid * 16;
    #pragma unroll
    for (int ks = 0; ks < 4; ks++)
        ldsm4(qf[ks], sb + AT_QOFF + (uint32_t)((wq0 + (lane & 15)) * AT_ROW)
                        + ks * 32 + (lane >> 4) * 16);

    float o[8][4] = {};
    float l0 = 0.f, l1 = 0.f;

    for (int c = 0; c < 16; c++) {
        if (c < 15) { CP_WAIT(1); } else { CP_WAIT(0); }
        __syncthreads();                 // all warps done with stage (c+2)%3's prior use
        if (c + 2 < 16) {
            load_chunk(sb + (uint32_t)((c + 2) % 3) * AT_STAGE, (c + 2) * 64);
            CP_COMMIT();
        }
        const uint32_t so = sb + (uint32_t)(c % 3) * AT_STAGE;

        // scores: Qh . Kh — p-pairs: 4 independent accumulators in flight
        float sc[8][4] = {};
        #pragma unroll
        for (int ks = 0; ks < 4; ks++) {
            #pragma unroll
            for (int pp = 0; pp < 2; pp++) {
                unsigned kh4a[4], kh4b[4];
                uint32_t roa = (uint32_t)(((2 * pp) * 16 + (lane >> 4) * 8 + (lane & 7)) * AT_ROW)
                             + ks * 32 + ((lane >> 3) & 1) * 16;
                uint32_t rob = roa + 16 * AT_ROW;
                ldsm4(kh4a, so + roa);
                ldsm4(kh4b, so + rob);
                mma16816(sc[4 * pp + 0], qf[ks], &kh4a[0]);
                mma16816(sc[4 * pp + 1], qf[ks], &kh4a[2]);
                mma16816(sc[4 * pp + 2], qf[ks], &kh4b[0]);
                mma16816(sc[4 * pp + 3], qf[ks], &kh4b[2]);
            }
        }

        // exp (bounded scores -> no running max), row sums
        float ev[8][4];
        #pragma unroll
        for (int nt = 0; nt < 8; nt++) {
            ev[nt][0] = __expf(sc[nt][0] * 0.125f);
            ev[nt][1] = __expf(sc[nt][1] * 0.125f);
            ev[nt][2] = __expf(sc[nt][2] * 0.125f);
            ev[nt][3] = __expf(sc[nt][3] * 0.125f);
            l0 += ev[nt][0] + ev[nt][1];
            l1 += ev[nt][2] + ev[nt][3];
        }

        // O += Ph·(Vh+Vl) + Pl·Vh — p-pairs, term-major (4 indep accs per term)
        #pragma unroll
        for (int ts = 0; ts < 4; ts++) {
            unsigned ph[4], pl[4];
            split2(ev[2 * ts][0],     ev[2 * ts][1],     ph[0], pl[0]);
            split2(ev[2 * ts][2],     ev[2 * ts][3],     ph[1], pl[1]);
            split2(ev[2 * ts + 1][0], ev[2 * ts + 1][1], ph[2], pl[2]);
            split2(ev[2 * ts + 1][2], ev[2 * ts + 1][3], ph[3], pl[3]);
            #pragma unroll
            for (int pp = 0; pp < 2; pp++) {
                uint32_t roa = (uint32_t)((ts * 16 + ((lane >> 3) & 1) * 8 + (lane & 7)) * AT_ROW)
                             + ((2 * pp) * 16 + (lane >> 4) * 8) * 2;
                uint32_t rob = roa + 32;
                unsigned vh4a[4], vl4a[4], vh4b[4], vl4b[4];
                ldsm4t(vh4a, so + 1 * AT_ARR + roa);
                ldsm4t(vl4a, so + 2 * AT_ARR + roa);
                ldsm4t(vh4b, so + 1 * AT_ARR + rob);
                ldsm4t(vl4b, so + 2 * AT_ARR + rob);
                // term 1: Ph . Vh
                mma16816(o[4 * pp + 0], ph, &vh4a[0]);
                mma16816(o[4 * pp + 1], ph, &vh4a[2]);
                mma16816(o[4 * pp + 2], ph, &vh4b[0]);
                mma16816(o[4 * pp + 3], ph, &vh4b[2]);
                // term 2: Ph . Vl
                mma16816(o[4 * pp + 0], ph, &vl4a[0]);
                mma16816(o[4 * pp + 1], ph, &vl4a[2]);
                mma16816(o[4 * pp + 2], ph, &vl4b[0]);
                mma16816(o[4 * pp + 3], ph, &vl4b[2]);
                // term 3: Pl . Vh
                mma16816(o[4 * pp + 0], pl, &vh4a[0]);
                mma16816(o[4 * pp + 1], pl, &vh4a[2]);
                mma16816(o[4 * pp + 2], pl, &vh4b[0]);
                mma16816(o[4 * pp + 3], pl, &vh4b[2]);
            }
        }
    }

    // softmax denominators: reduce col-pairs across the quad
    l0 += __shfl_xor_sync(0xffffffffu, l0, 1);
    l0 += __shfl_xor_sync(0xffffffffu, l0, 2);
    l1 += __shfl_xor_sync(0xffffffffu, l1, 1);
    l1 += __shfl_xor_sync(0xffffffffu, l1, 2);
    float inv0 = 1.0f / l0, inv1 = 1.0f / l1;

    const int r0 = lane >> 2, c0 = lane & 3;
    int sA = s0 + wq0 + r0;
    size_t mA = ((size_t)sA * BB + b) * (HH * KK);
    size_t mB = ((size_t)(sA + 8) * BB + b) * (HH * KK);
    #pragma unroll
    for (int nk = 0; nk < 8; nk++) {
        int j = h * KK + nk * 8 + 2 * c0;
        unsigned h0, lo0, h1, lo1;
        split2(o[nk][0] * inv0, o[nk][1] * inv0, h0, lo0);
        split2(o[nk][2] * inv1, o[nk][3] * inv1, h1, lo1);
        *(unsigned*)&g_ath[mA + j] = h0;
        *(unsigned*)&g_atl[mA + j] = lo0;
        *(unsigned*)&g_ath[mB + j] = h1;
        *(unsigned*)&g_atl[mB + j] = lo1;
    }
}

// ---------------------------------------------------------------------------
extern "C" void kernel_launch(void* const* d_in, const int* in_sizes, int n_in,
                              void* d_out, int out_size)
{
    const float* q    = (const float*)d_in[0];
    const float* k    = (const float*)d_in[1];
    const float* v    = (const float*)d_in[2];
    const float* WQ   = (const float*)d_in[3];
    const float* WK   = (const float*)d_in[4];
    const float* WV   = (const float*)d_in[5];
    const float* Wout = (const float*)d_in[6];
    float* out = (float*)d_out;

    cudaFuncSetAttribute(proj_mma,
                         cudaFuncAttributeMaxDynamicSharedMemorySize, MMA_SMEM);
    cudaFuncSetAttribute(outproj_mma,
                         cudaFuncAttributeMaxDynamicSharedMemorySize, MMA_SMEM);
    cudaFuncSetAttribute(attn_mma,
                         cudaFuncAttributeMaxDynamicSharedMemorySize, ATT_SMEM);

    cvt_all<<<dim3(1024, 1, 7), 256>>>((const float4*)q, (const float4*)k,
                                       (const float4*)v, (const float4*)WQ,
                                       (const float4*)WK, (const float4*)WV,
                                       (const float4*)Wout);
    proj_mma<<<dim3(12, 128), 256, MMA_SMEM>>>();
    attn_mma<<<dim3(SS / 128, BB * HH), 256, ATT_SMEM>>>();
    outproj_mma<<<dim3(4, 128), 256, MMA_SMEM>>>(out);
}

// round 16
// speedup vs baseline: 1.4310x; 1.0194x over previous
#include <cuda_runtime.h>
#include <cuda_bf16.h>
#include <math.h>
#include <stdint.h>

#define SS 1024
#define BB 16
#define DD 512
#define HH 8
#define KK 64

using ull = unsigned long long;

// bf16 hi/lo splits of inputs & weights (for proj / outproj GEMMs)
__device__ __nv_bfloat16 g_ih[3 * SS * BB * DD];   // q,k,v inputs [t][m=s*16+b][d]
__device__ __nv_bfloat16 g_il[3 * SS * BB * DD];   // lo used only for v (t=2)
__device__ __nv_bfloat16 g_wh[3 * DD * DD];        // WQ,WK,WV [t][n][d]
__device__ __nv_bfloat16 g_wl[3 * DD * DD];        // lo used only for WV
__device__ __nv_bfloat16 g_oh[DD * DD];            // Wout [n][j]
__device__ __nv_bfloat16 g_ol[DD * DD];
// normalized projections, bf16, [bh][s][k]  (K hi only; V hi+lo)
__device__ __nv_bfloat16 g_qh[BB * HH * SS * KK];
__device__ __nv_bfloat16 g_kh[BB * HH * SS * KK];
__device__ __nv_bfloat16 g_vh[BB * HH * SS * KK];
__device__ __nv_bfloat16 g_vl[BB * HH * SS * KK];
// column sums of V per (bh,k): SV[bh][k] = sum_s v  (for P = 1 + P' softmax)
__device__ float g_sv[BB * HH * KK];
// attention output [m = s*16+b][j = h*64+k], bf16 hi/lo
__device__ __nv_bfloat16 g_ath[SS * BB * HH * KK];
__device__ __nv_bfloat16 g_atl[SS * BB * HH * KK];

// ---------------------------------------------------------------------------
// helpers
// ---------------------------------------------------------------------------
__device__ __forceinline__ uint32_t smem_u32(const void* p) {
    uint32_t a;
    asm("{ .reg .u64 t; cvta.to.shared.u64 t, %1; cvt.u32.u64 %0, t; }"
        : "=r"(a) : "l"(p));
    return a;
}

__device__ __forceinline__ unsigned bpack(float lo_elem, float hi_elem) {
    unsigned r;  // lower 16 = bf16(lo_elem), upper 16 = bf16(hi_elem)
    asm("cvt.rn.bf16x2.f32 %0, %1, %2;" : "=r"(r) : "f"(hi_elem), "f"(lo_elem));
    return r;
}
__device__ __forceinline__ void split2(float x, float y, unsigned& hi, unsigned& lo) {
    unsigned h = bpack(x, y);
    float hx = __uint_as_float(h << 16);
    float hy = __uint_as_float(h & 0xffff0000u);
    hi = h;
    lo = bpack(x - hx, y - hy);
}

__device__ __forceinline__ void ldsm4(unsigned* r, uint32_t addr) {
    asm volatile("ldmatrix.sync.aligned.m8n8.x4.shared.b16 {%0,%1,%2,%3}, [%4];"
                 : "=r"(r[0]), "=r"(r[1]), "=r"(r[2]), "=r"(r[3]) : "r"(addr));
}
__device__ __forceinline__ void ldsm4t(unsigned* r, uint32_t addr) {
    asm volatile("ldmatrix.sync.aligned.m8n8.x4.trans.shared.b16 {%0,%1,%2,%3}, [%4];"
                 : "=r"(r[0]), "=r"(r[1]), "=r"(r[2]), "=r"(r[3]) : "r"(addr));
}
// non-volatile: pure register computation, lets ptxas interleave MMAs.
__device__ __forceinline__ void mma16816(float* d, const unsigned* a, const unsigned* b) {
    asm("mma.sync.aligned.m16n8k16.row.col.f32.bf16.bf16.f32 "
        "{%0,%1,%2,%3}, {%4,%5,%6,%7}, {%8,%9}, {%0,%1,%2,%3};"
        : "+f"(d[0]), "+f"(d[1]), "+f"(d[2]), "+f"(d[3])
        : "r"(a[0]), "r"(a[1]), "r"(a[2]), "r"(a[3]), "r"(b[0]), "r"(b[1]));
}
__device__ __forceinline__ void cpasync16(uint32_t saddr, const void* gaddr) {
    asm volatile("cp.async.ca.shared.global [%0], [%1], 16;"
                 :: "r"(saddr), "l"(gaddr) : "memory");
}
#define CP_COMMIT() asm volatile("cp.async.commit_group;" ::: "memory")
#define CP_WAIT(n)  asm volatile("cp.async.wait_group %0;" :: "n"(n) : "memory")

// GEMM smem layout (R11-proven): rows of 32 bf16 padded to 80B, 2 stages, KC=32
#define ROW_B   80
#define ARR_B   10240
#define B_HI    20480
#define B_LO    30720
#define STAGE_B 40960
#define MMA_SMEM (2 * STAGE_B)

// ---------------------------------------------------------------------------
// fused convert: fp32 -> bf16 hi/lo, one launch, z selects array.
// lo residues are skipped where never read (q,k inputs; WQ,WK).
// ---------------------------------------------------------------------------
__global__ void cvt_all(const float4* __restrict__ q, const float4* __restrict__ k,
                        const float4* __restrict__ v, const float4* __restrict__ wq,
                        const float4* __restrict__ wk, const float4* __restrict__ wv,
                        const float4* __restrict__ wo)
{
    const int NIN = SS * BB * DD / 4, NW = DD * DD / 4;
    const int z = blockIdx.z;
    const float4* src;
    uint2 *hi, *lo;
    int n4;
    bool wlo = true;
    switch (z) {
        case 0: src = q;  hi = (uint2*)g_ih;           lo = (uint2*)g_il;           n4 = NIN; wlo = false; break;
        case 1: src = k;  hi = (uint2*)g_ih + NIN;     lo = (uint2*)g_il + NIN;     n4 = NIN; wlo = false; break;
        case 2: src = v;  hi = (uint2*)g_ih + 2 * NIN; lo = (uint2*)g_il + 2 * NIN; n4 = NIN; break;
        case 3: src = wq; hi = (uint2*)g_wh;           lo = (uint2*)g_wl;           n4 = NW;  wlo = false; break;
        case 4: src = wk; hi = (uint2*)g_wh + NW;      lo = (uint2*)g_wl + NW;      n4 = NW;  wlo = false; break;
        case 5: src = wv; hi = (uint2*)g_wh + 2 * NW;  lo = (uint2*)g_wl + 2 * NW;  n4 = NW;  break;
        default: src = wo; hi = (uint2*)g_oh;          lo = (uint2*)g_ol;           n4 = NW;  break;
    }
    for (int i = blockIdx.x * blockDim.x + threadIdx.x; i < n4;
         i += gridDim.x * blockDim.x) {
        float4 x = src[i];
        unsigned h0, l0, h1, l1;
        split2(x.x, x.y, h0, l0);
        split2(x.z, x.w, h1, l1);
        hi[i] = make_uint2(h0, h1);
        if (wlo) lo[i] = make_uint2(l0, l1);
    }
}

// ---------------------------------------------------------------------------
// SV[bh][k] = sum_s (vh + vl), fp32.  grid = 128 blocks, 256 threads.
// ---------------------------------------------------------------------------
__global__ void sum_v()
{
    const int bh = blockIdx.x;
    const int tid = threadIdx.x;
    const int k = tid & 63, part = tid >> 6;    // 4 parts x 256 rows
    const __nv_bfloat16* vh = g_vh + (size_t)bh * SS * KK;
    const __nv_bfloat16* vl = g_vl + (size_t)bh * SS * KK;
    float s = 0.f;
    for (int r = part * 256; r < part * 256 + 256; r++)
        s += __bfloat162float(vh[(size_t)r * KK + k]) +
             __bfloat162float(vl[(size_t)r * KK + k]);
    __shared__ float red[256];
    red[tid] = s;
    __syncthreads();
    if (part == 0)
        g_sv[bh * KK + k] = red[k] + red[64 + k] + red[128 + k] + red[192 + k];
}

// ---------------------------------------------------------------------------
// shared mma mainloop (R11 2-stage KC=32), templated on term count.
// NT=3: d += Ah·Bh + Ah·Bl + Al·Bh.   NT=1: d += Ah·Bh (half the loads too).
// ---------------------------------------------------------------------------
struct MmaCtx {
    float d[2][8][4];
    uint32_t aHi[2], aLo[2], bHi[4], bLo[4];
};

template <int NT>
__device__ __forceinline__ void mma_mainloop(
    MmaCtx& cx, uint32_t sb,
    const __nv_bfloat16* srcAh, const __nv_bfloat16* srcAl,
    const __nv_bfloat16* srcBh, const __nv_bfloat16* srcBl)
{
    const int tid = threadIdx.x;
    const int wid = tid >> 5, lane = tid & 31;
    const int wm = (wid & 3) * 32, wn = (wid >> 2) * 64;

    #pragma unroll
    for (int mb = 0; mb < 2; mb++) {
        uint32_t ro = (uint32_t)(wm + mb * 16 + (lane & 15)) * ROW_B + (lane >> 4) * 16;
        cx.aHi[mb] = sb + ro;
        cx.aLo[mb] = sb + ARR_B + ro;
    }
    #pragma unroll
    for (int p = 0; p < 4; p++) {
        uint32_t ro = (uint32_t)(wn + p * 16 + (lane >> 4) * 8 + (lane & 7)) * ROW_B
                    + ((lane >> 3) & 1) * 16;
        cx.bHi[p] = sb + B_HI + ro;
        cx.bLo[p] = sb + B_LO + ro;
    }
    #pragma unroll
    for (int mb = 0; mb < 2; mb++)
        #pragma unroll
        for (int nb = 0; nb < 8; nb++)
            #pragma unroll
            for (int e = 0; e < 4; e++) cx.d[mb][nb][e] = 0.f;

    // loader: NT=3 -> 4 arrays (Ah,Al,Bh,Bl); NT=1 -> 2 arrays (Ah,Bh)
    constexpr int NCH = (NT == 3) ? 8 : 4;
    auto load_stage = [&](uint32_t stb, int k0) {
        #pragma unroll
        for (int i = 0; i < NCH; i++) {
            int idx = tid + i * 256;
            int a = idx >> 9, ci = idx & 511, r = ci >> 2, cc = ci & 3;
            const __nv_bfloat16* s;
            uint32_t aoff;
            if (NT == 3) {
                s = (a == 0) ? srcAh : (a == 1) ? srcAl : (a == 2) ? srcBh : srcBl;
                aoff = (uint32_t)a * ARR_B;
            } else {
                s = (a == 0) ? srcAh : srcBh;
                aoff = (a == 0) ? 0u : (uint32_t)B_HI;
            }
            cpasync16(stb + aoff + (uint32_t)(r * ROW_B + cc * 16),
                      s + (size_t)r * DD + k0 + cc * 8);
        }
        CP_COMMIT();
    };

    load_stage(sb, 0);

    for (int it = 0; it < 16; it++) {
        if (it + 1 < 16) {
            load_stage(sb + (uint32_t)((it + 1) & 1) * STAGE_B, (it + 1) * 32);
            CP_WAIT(1);
        } else {
            CP_WAIT(0);
        }
        __syncthreads();

        const uint32_t so = (uint32_t)(it & 1) * STAGE_B;
        #pragma unroll
        for (int ks = 0; ks < 2; ks++) {
            const uint32_t off = so + ks * 32;
            unsigned ah[2][4], al[2][4];
            #pragma unroll
            for (int mb = 0; mb < 2; mb++) {
                ldsm4(ah[mb], cx.aHi[mb] + off);
                if (NT == 3) ldsm4(al[mb], cx.aLo[mb] + off);
            }
            #pragma unroll
            for (int p = 0; p < 4; p++) {
                unsigned tbh[4], tbl[4];
                ldsm4(tbh, cx.bHi[p] + off);
                if (NT == 3) ldsm4(tbl, cx.bLo[p] + off);
                #pragma unroll
                for (int mb = 0; mb < 2; mb++)
                    #pragma unroll
                    for (int qn = 0; qn < 2; qn++)
                        mma16816(cx.d[mb][2 * p + qn], ah[mb], &tbh[2 * qn]);
                if (NT == 3) {
                    #pragma unroll
                    for (int mb = 0; mb < 2; mb++)
                        #pragma unroll
                        for (int qn = 0; qn < 2; qn++)
                            mma16816(cx.d[mb][2 * p + qn], ah[mb], &tbl[2 * qn]);
                    #pragma unroll
                    for (int mb = 0; mb < 2; mb++)
                        #pragma unroll
                        for (int qn = 0; qn < 2; qn++)
                            mma16816(cx.d[mb][2 * p + qn], al[mb], &tbh[2 * qn]);
                }
            }
        }
        __syncthreads();
    }
}

// ---------------------------------------------------------------------------
// projection + L2 norm -> bf16 outputs in [bh][s][k]
// Q,K: 1-term GEMM.  V: 3-term GEMM.
// ---------------------------------------------------------------------------
__global__ __launch_bounds__(256) void proj_mma()
{
    extern __shared__ __align__(16) char dsm[];
    const uint32_t sb = smem_u32(dsm);

    const int n0 = blockIdx.x * 128;
    const int m0 = blockIdx.y * 128;
    const int t  = n0 >> 9;
    const int nr = n0 & 511;

    const __nv_bfloat16* srcAh = g_ih + (size_t)t * (SS * BB * DD) + (size_t)m0 * DD;
    const __nv_bfloat16* srcAl = g_il + (size_t)t * (SS * BB * DD) + (size_t)m0 * DD;
    const __nv_bfloat16* srcBh = g_wh + (size_t)t * (DD * DD) + (size_t)nr * DD;
    const __nv_bfloat16* srcBl = g_wl + (size_t)t * (DD * DD) + (size_t)nr * DD;

    __nv_bfloat16* dsth = (t == 0) ? g_qh : (t == 1) ? g_kh : g_vh;
    __nv_bfloat16* dstl = g_vl;
    const bool write_lo = (t == 2);     // only V needs the lo residue

    MmaCtx cx;
    if (t == 2) mma_mainloop<3>(cx, sb, srcAh, srcAl, srcBh, srcBl);
    else        mma_mainloop<1>(cx, sb, srcAh, srcAl, srcBh, srcBl);

    const int tid = threadIdx.x;
    const int wid = tid >> 5, lane = tid & 31;
    const int wm = (wid & 3) * 32, wn = (wid >> 2) * 64;
    const int r0 = lane >> 2, c0 = lane & 3;
    const int h = (nr >> 6) + (wn >> 6);

    #pragma unroll
    for (int mb = 0; mb < 2; mb++) {
        float ssa = 0.f, ssb = 0.f;
        #pragma unroll
        for (int nb = 0; nb < 8; nb++) {
            float* d = cx.d[mb][nb];
            ssa = fmaf(d[0], d[0], fmaf(d[1], d[1], ssa));
            ssb = fmaf(d[2], d[2], fmaf(d[3], d[3], ssb));
        }
        ssa += __shfl_xor_sync(0xffffffffu, ssa, 1);
        ssa += __shfl_xor_sync(0xffffffffu, ssa, 2);
        ssb += __shfl_xor_sync(0xffffffffu, ssb, 1);
        ssb += __shfl_xor_sync(0xffffffffu, ssb, 2);
        float inva = 1.0f / fmaxf(sqrtf(ssa), 1e-12f);
        float invb = 1.0f / fmaxf(sqrtf(ssb), 1e-12f);

        int ma = m0 + wm + mb * 16 + r0;
        int mb2 = ma + 8;
        int ba = ma & 15, sa = ma >> 4;
        int bbb = mb2 & 15, sbb = mb2 >> 4;
        size_t rowA = (((size_t)(ba * HH + h)) * SS + sa) * KK;
        size_t rowB = (((size_t)(bbb * HH + h)) * SS + sbb) * KK;
        #pragma unroll
        for (int nb = 0; nb < 8; nb++) {
            int kk = ((wn & 63) + nb * 8 + 2 * c0);
            float* d = cx.d[mb][nb];
            unsigned hA, lA, hB, lB;
            split2(d[0] * inva, d[1] * inva, hA, lA);
            split2(d[2] * invb, d[3] * invb, hB, lB);
            *(unsigned*)&dsth[rowA + kk] = hA;
            *(unsigned*)&dsth[rowB + kk] = hB;
            if (write_lo) {
                *(unsigned*)&dstl[rowA + kk] = lA;
                *(unsigned*)&dstl[rowB + kk] = lB;
            }
        }
    }
}

// ---------------------------------------------------------------------------
// output projection: out[m][n] fp32 (3-term)
// ---------------------------------------------------------------------------
__global__ __launch_bounds__(256) void outproj_mma(float* __restrict__ out)
{
    extern __shared__ __align__(16) char dsm[];
    const uint32_t sb = smem_u32(dsm);

    const int n0 = blockIdx.x * 128;
    const int m0 = blockIdx.y * 128;

    MmaCtx cx;
    mma_mainloop<3>(cx, sb, g_ath + (size_t)m0 * DD, g_atl + (size_t)m0 * DD,
                    g_oh + (size_t)n0 * DD, g_ol + (size_t)n0 * DD);

    const int tid = threadIdx.x;
    const int wid = tid >> 5, lane = tid & 31;
    const int wm = (wid & 3) * 32, wn = (wid >> 2) * 64;
    const int r0 = lane >> 2, c0 = lane & 3;

    #pragma unroll
    for (int mb = 0; mb < 2; mb++) {
        int ma = m0 + wm + mb * 16 + r0;
        float* pa = out + (size_t)ma * DD;
        float* pb = out + (size_t)(ma + 8) * DD;
        #pragma unroll
        for (int nb = 0; nb < 8; nb++) {
            int n = n0 + wn + nb * 8 + 2 * c0;
            float* d = cx.d[mb][nb];
            *(float2*)&pa[n] = make_float2(d[0], d[1]);
            *(float2*)&pb[n] = make_float2(d[2], d[3]);
        }
    }
}

// ---------------------------------------------------------------------------
// attention via mma.sync, P = 1 + P' decomposition:
//   p' = exp(s/8) - 1, |p'| <= 0.13  ->  bf16(p') abs err ~2e-4 (8x smaller
//   than bf16(p)), so single-term P' suffices:  O = SV + P'·(Vh+Vl),
//   l = 1024 + sum(p').  Saves the Pl·Vh term: 96 -> 64 PV MMAs per chunk.
// ---------------------------------------------------------------------------
#define AT_ROW   144
#define AT_ARR   (64 * AT_ROW)        // 9216
#define AT_STAGE (3 * AT_ARR)         // 27648
#define AT_QOFF  (3 * AT_STAGE)       // 82944
#define ATT_SMEM (AT_QOFF + 128 * AT_ROW)   // 101376

__global__ __launch_bounds__(256, 2) void attn_mma()
{
    extern __shared__ __align__(16) char dsm[];
    const uint32_t sb = smem_u32(dsm);

    const int tid = threadIdx.x, wid = tid >> 5, lane = tid & 31;
    const int s0 = blockIdx.x * 128;
    const int bh = blockIdx.y;
    const int b = bh >> 3, h = bh & 7;

    const __nv_bfloat16* qh = g_qh + (size_t)bh * SS * KK + (size_t)s0 * KK;
    const __nv_bfloat16* kh = g_kh + (size_t)bh * SS * KK;
    const __nv_bfloat16* vh = g_vh + (size_t)bh * SS * KK;
    const __nv_bfloat16* vl = g_vl + (size_t)bh * SS * KK;

    // chunk loader: kh,vh,vl tiles of 64 rows x 64 bf16 (6 chunks/thread)
    auto load_chunk = [&](uint32_t stb, int t0) {
        #pragma unroll
        for (int i = 0; i < 6; i++) {
            int idx = tid + i * 256;
            int a = idx >> 9, ci = idx & 511, r = ci >> 3, c = ci & 7;
            const __nv_bfloat16* s = (a == 0) ? kh : (a == 1) ? vh : vl;
            cpasync16(stb + a * AT_ARR + (uint32_t)(r * AT_ROW + c * 16),
                      s + (size_t)(t0 + r) * KK + c * 8);
        }
    };

    // group 0: Q tile (hi only), 128 rows x 64 bf16
    #pragma unroll
    for (int i = 0; i < 4; i++) {
        int idx = tid + i * 256;
        int r = idx >> 3, c = idx & 7;
        cpasync16(sb + AT_QOFF + (uint32_t)(r * AT_ROW + c * 16),
                  qh + (size_t)r * KK + c * 8);
    }
    CP_COMMIT();
    // groups 1,2: chunks 0,1
    load_chunk(sb, 0); CP_COMMIT();
    load_chunk(sb + AT_STAGE, 64); CP_COMMIT();

    CP_WAIT(2);          // Q ready
    __syncthreads();
    unsigned qf[4][4];
    const int wq0 = wid * 16;
    #pragma unroll
    for (int ks = 0; ks < 4; ks++)
        ldsm4(qf[ks], sb + AT_QOFF + (uint32_t)((wq0 + (lane & 15)) * AT_ROW)
                        + ks * 32 + (lane >> 4) * 16);

    float o[8][4] = {};
    float l0 = 0.f, l1 = 0.f;     // sums of p'

    for (int c = 0; c < 16; c++) {
        if (c < 15) { CP_WAIT(1); } else { CP_WAIT(0); }
        __syncthreads();                 // all warps done with stage (c+2)%3's prior use
        if (c + 2 < 16) {
            load_chunk(sb + (uint32_t)((c + 2) % 3) * AT_STAGE, (c + 2) * 64);
            CP_COMMIT();
        }
        const uint32_t so = sb + (uint32_t)(c % 3) * AT_STAGE;

        // scores: Qh . Kh — p-pairs: 4 independent accumulators in flight
        float sc[8][4] = {};
        #pragma unroll
        for (int ks = 0; ks < 4; ks++) {
            #pragma unroll
            for (int pp = 0; pp < 2; pp++) {
                unsigned kh4a[4], kh4b[4];
                uint32_t roa = (uint32_t)(((2 * pp) * 16 + (lane >> 4) * 8 + (lane & 7)) * AT_ROW)
                             + ks * 32 + ((lane >> 3) & 1) * 16;
                uint32_t rob = roa + 16 * AT_ROW;
                ldsm4(kh4a, so + roa);
                ldsm4(kh4b, so + rob);
                mma16816(sc[4 * pp + 0], qf[ks], &kh4a[0]);
                mma16816(sc[4 * pp + 1], qf[ks], &kh4a[2]);
                mma16816(sc[4 * pp + 2], qf[ks], &kh4b[0]);
                mma16816(sc[4 * pp + 3], qf[ks], &kh4b[2]);
            }
        }

        // p' = exp(s/8) - 1 (bounded, no running max), accumulate sum(p')
        float ev[8][4];
        #pragma unroll
        for (int nt = 0; nt < 8; nt++) {
            ev[nt][0] = __expf(sc[nt][0] * 0.125f) - 1.0f;
            ev[nt][1] = __expf(sc[nt][1] * 0.125f) - 1.0f;
            ev[nt][2] = __expf(sc[nt][2] * 0.125f) - 1.0f;
            ev[nt][3] = __expf(sc[nt][3] * 0.125f) - 1.0f;
            l0 += ev[nt][0] + ev[nt][1];
            l1 += ev[nt][2] + ev[nt][3];
        }

        // O += P'h·(Vh+Vl) — p-pairs, term-major (4 indep accs per term)
        #pragma unroll
        for (int ts = 0; ts < 4; ts++) {
            unsigned ph[4];
            ph[0] = bpack(ev[2 * ts][0],     ev[2 * ts][1]);
            ph[1] = bpack(ev[2 * ts][2],     ev[2 * ts][3]);
            ph[2] = bpack(ev[2 * ts + 1][0], ev[2 * ts + 1][1]);
            ph[3] = bpack(ev[2 * ts + 1][2], ev[2 * ts + 1][3]);
            #pragma unroll
            for (int pp = 0; pp < 2; pp++) {
                uint32_t roa = (uint32_t)((ts * 16 + ((lane >> 3) & 1) * 8 + (lane & 7)) * AT_ROW)
                             + ((2 * pp) * 16 + (lane >> 4) * 8) * 2;
                uint32_t rob = roa + 32;
                unsigned vh4a[4], vl4a[4], vh4b[4], vl4b[4];
                ldsm4t(vh4a, so + 1 * AT_ARR + roa);
                ldsm4t(vl4a, so + 2 * AT_ARR + roa);
                ldsm4t(vh4b, so + 1 * AT_ARR + rob);
                ldsm4t(vl4b, so + 2 * AT_ARR + rob);
                // term 1: P'h . Vh
                mma16816(o[4 * pp + 0], ph, &vh4a[0]);
                mma16816(o[4 * pp + 1], ph, &vh4a[2]);
                mma16816(o[4 * pp + 2], ph, &vh4b[0]);
                mma16816(o[4 * pp + 3], ph, &vh4b[2]);
                // term 2: P'h . Vl
                mma16816(o[4 * pp + 0], ph, &vl4a[0]);
                mma16816(o[4 * pp + 1], ph, &vl4a[2]);
                mma16816(o[4 * pp + 2], ph, &vl4b[0]);
                mma16816(o[4 * pp + 3], ph, &vl4b[2]);
            }
        }
    }

    // denominators: l = 1024 + sum(p'); reduce col-pairs across the quad
    l0 += __shfl_xor_sync(0xffffffffu, l0, 1);
    l0 += __shfl_xor_sync(0xffffffffu, l0, 2);
    l1 += __shfl_xor_sync(0xffffffffu, l1, 1);
    l1 += __shfl_xor_sync(0xffffffffu, l1, 2);
    float inv0 = 1.0f / (1024.0f + l0);
    float inv1 = 1.0f / (1024.0f + l1);

    const int r0 = lane >> 2, c0 = lane & 3;
    int sA = s0 + wq0 + r0;
    size_t mA = ((size_t)sA * BB + b) * (HH * KK);
    size_t mB = ((size_t)(sA + 8) * BB + b) * (HH * KK);
    const float* svp = g_sv + bh * KK;
    #pragma unroll
    for (int nk = 0; nk < 8; nk++) {
        int kk = nk * 8 + 2 * c0;
        int j = h * KK + kk;
        float2 sv = *(const float2*)&svp[kk];
        unsigned h0, lo0, h1, lo1;
        split2((sv.x + o[nk][0]) * inv0, (sv.y + o[nk][1]) * inv0, h0, lo0);
        split2((sv.x + o[nk][2]) * inv1, (sv.y + o[nk][3]) * inv1, h1, lo1);
        *(unsigned*)&g_ath[mA + j] = h0;
        *(unsigned*)&g_atl[mA + j] = lo0;
        *(unsigned*)&g_ath[mB + j] = h1;
        *(unsigned*)&g_atl[mB + j] = lo1;
    }
}

// ---------------------------------------------------------------------------
extern "C" void kernel_launch(void* const* d_in, const int* in_sizes, int n_in,
                              void* d_out, int out_size)
{
    const float* q    = (const float*)d_in[0];
    const float* k    = (const float*)d_in[1];
    const float* v    = (const float*)d_in[2];
    const float* WQ   = (const float*)d_in[3];
    const float* WK   = (const float*)d_in[4];
    const float* WV   = (const float*)d_in[5];
    const float* Wout = (const float*)d_in[6];
    float* out = (float*)d_out;

    cudaFuncSetAttribute(proj_mma,
                         cudaFuncAttributeMaxDynamicSharedMemorySize, MMA_SMEM);
    cudaFuncSetAttribute(outproj_mma,
                         cudaFuncAttributeMaxDynamicSharedMemorySize, MMA_SMEM);
    cudaFuncSetAttribute(attn_mma,
                         cudaFuncAttributeMaxDynamicSharedMemorySize, ATT_SMEM);

    cvt_all<<<dim3(1024, 1, 7), 256>>>((const float4*)q, (const float4*)k,
                                       (const float4*)v, (const float4*)WQ,
                                       (const float4*)WK, (const float4*)WV,
                                       (const float4*)Wout);
    proj_mma<<<dim3(12, 128), 256, MMA_SMEM>>>();
    sum_v<<<BB * HH, 256>>>();
    attn_mma<<<dim3(SS / 128, BB * HH), 256, ATT_SMEM>>>();
    outproj_mma<<<dim3(4, 128), 256, MMA_SMEM>>>(out);
}

// round 17
// speedup vs baseline: 1.5875x; 1.1093x over previous
#include <cuda_runtime.h>
#include <cuda_bf16.h>
#include <math.h>
#include <stdint.h>

#define SS 1024
#define BB 16
#define DD 512
#define HH 8
#define KK 64

using ull = unsigned long long;

// bf16 hi/lo splits of inputs & weights (for proj / outproj GEMMs)
__device__ __nv_bfloat16 g_ih[3 * SS * BB * DD];   // q,k,v inputs [t][m=s*16+b][d]
__device__ __nv_bfloat16 g_il[3 * SS * BB * DD];   // lo used only for v (t=2)
__device__ __nv_bfloat16 g_wh[3 * DD * DD];        // WQ,WK,WV [t][n][d]
__device__ __nv_bfloat16 g_wl[3 * DD * DD];        // lo used only for WV
__device__ __nv_bfloat16 g_oh[DD * DD];            // Wout [n][j]
__device__ __nv_bfloat16 g_ol[DD * DD];
// normalized projections, bf16, [bh][s][k]
// (K hi only; V hi for PV; V lo only feeds the exact SV column sums)
__device__ __nv_bfloat16 g_qh[BB * HH * SS * KK];
__device__ __nv_bfloat16 g_kh[BB * HH * SS * KK];
__device__ __nv_bfloat16 g_vh[BB * HH * SS * KK];
__device__ __nv_bfloat16 g_vl[BB * HH * SS * KK];
// column sums of V per (bh,k): SV[bh][k] = sum_s v  (for P = 1 + P' softmax)
__device__ float g_sv[BB * HH * KK];
// attention output [m = s*16+b][j = h*64+k], bf16 hi/lo
__device__ __nv_bfloat16 g_ath[SS * BB * HH * KK];
__device__ __nv_bfloat16 g_atl[SS * BB * HH * KK];

// ---------------------------------------------------------------------------
// helpers
// ---------------------------------------------------------------------------
__device__ __forceinline__ uint32_t smem_u32(const void* p) {
    uint32_t a;
    asm("{ .reg .u64 t; cvta.to.shared.u64 t, %1; cvt.u32.u64 %0, t; }"
        : "=r"(a) : "l"(p));
    return a;
}

__device__ __forceinline__ unsigned bpack(float lo_elem, float hi_elem) {
    unsigned r;  // lower 16 = bf16(lo_elem), upper 16 = bf16(hi_elem)
    asm("cvt.rn.bf16x2.f32 %0, %1, %2;" : "=r"(r) : "f"(hi_elem), "f"(lo_elem));
    return r;
}
__device__ __forceinline__ void split2(float x, float y, unsigned& hi, unsigned& lo) {
    unsigned h = bpack(x, y);
    float hx = __uint_as_float(h << 16);
    float hy = __uint_as_float(h & 0xffff0000u);
    hi = h;
    lo = bpack(x - hx, y - hy);
}

__device__ __forceinline__ void ldsm4(unsigned* r, uint32_t addr) {
    asm volatile("ldmatrix.sync.aligned.m8n8.x4.shared.b16 {%0,%1,%2,%3}, [%4];"
                 : "=r"(r[0]), "=r"(r[1]), "=r"(r[2]), "=r"(r[3]) : "r"(addr));
}
__device__ __forceinline__ void ldsm4t(unsigned* r, uint32_t addr) {
    asm volatile("ldmatrix.sync.aligned.m8n8.x4.trans.shared.b16 {%0,%1,%2,%3}, [%4];"
                 : "=r"(r[0]), "=r"(r[1]), "=r"(r[2]), "=r"(r[3]) : "r"(addr));
}
// non-volatile: pure register computation, lets ptxas interleave MMAs.
__device__ __forceinline__ void mma16816(float* d, const unsigned* a, const unsigned* b) {
    asm("mma.sync.aligned.m16n8k16.row.col.f32.bf16.bf16.f32 "
        "{%0,%1,%2,%3}, {%4,%5,%6,%7}, {%8,%9}, {%0,%1,%2,%3};"
        : "+f"(d[0]), "+f"(d[1]), "+f"(d[2]), "+f"(d[3])
        : "r"(a[0]), "r"(a[1]), "r"(a[2]), "r"(a[3]), "r"(b[0]), "r"(b[1]));
}
__device__ __forceinline__ void cpasync16(uint32_t saddr, const void* gaddr) {
    asm volatile("cp.async.ca.shared.global [%0], [%1], 16;"
                 :: "r"(saddr), "l"(gaddr) : "memory");
}
#define CP_COMMIT() asm volatile("cp.async.commit_group;" ::: "memory")
#define CP_WAIT(n)  asm volatile("cp.async.wait_group %0;" :: "n"(n) : "memory")

// GEMM smem layout (R11-proven): rows of 32 bf16 padded to 80B, 2 stages, KC=32
#define ROW_B   80
#define ARR_B   10240
#define B_HI    20480
#define B_LO    30720
#define STAGE_B 40960
#define MMA_SMEM (2 * STAGE_B)

// ---------------------------------------------------------------------------
// fused convert: fp32 -> bf16 hi/lo, one launch, z selects array.
// lo residues are skipped where never read (q,k inputs; WQ,WK).
// ---------------------------------------------------------------------------
__global__ void cvt_all(const float4* __restrict__ q, const float4* __restrict__ k,
                        const float4* __restrict__ v, const float4* __restrict__ wq,
                        const float4* __restrict__ wk, const float4* __restrict__ wv,
                        const float4* __restrict__ wo)
{
    const int NIN = SS * BB * DD / 4, NW = DD * DD / 4;
    const int z = blockIdx.z;
    const float4* src;
    uint2 *hi, *lo;
    int n4;
    bool wlo = true;
    switch (z) {
        case 0: src = q;  hi = (uint2*)g_ih;           lo = (uint2*)g_il;           n4 = NIN; wlo = false; break;
        case 1: src = k;  hi = (uint2*)g_ih + NIN;     lo = (uint2*)g_il + NIN;     n4 = NIN; wlo = false; break;
        case 2: src = v;  hi = (uint2*)g_ih + 2 * NIN; lo = (uint2*)g_il + 2 * NIN; n4 = NIN; break;
        case 3: src = wq; hi = (uint2*)g_wh;           lo = (uint2*)g_wl;           n4 = NW;  wlo = false; break;
        case 4: src = wk; hi = (uint2*)g_wh + NW;      lo = (uint2*)g_wl + NW;      n4 = NW;  wlo = false; break;
        case 5: src = wv; hi = (uint2*)g_wh + 2 * NW;  lo = (uint2*)g_wl + 2 * NW;  n4 = NW;  break;
        default: src = wo; hi = (uint2*)g_oh;          lo = (uint2*)g_ol;           n4 = NW;  break;
    }
    for (int i = blockIdx.x * blockDim.x + threadIdx.x; i < n4;
         i += gridDim.x * blockDim.x) {
        float4 x = src[i];
        unsigned h0, l0, h1, l1;
        split2(x.x, x.y, h0, l0);
        split2(x.z, x.w, h1, l1);
        hi[i] = make_uint2(h0, h1);
        if (wlo) lo[i] = make_uint2(l0, l1);
    }
}

// ---------------------------------------------------------------------------
// SV[bh][k] = sum_s (vh + vl), fp32.  grid = 128 blocks, 256 threads.
// ---------------------------------------------------------------------------
__global__ void sum_v()
{
    const int bh = blockIdx.x;
    const int tid = threadIdx.x;
    const int k = tid & 63, part = tid >> 6;    // 4 parts x 256 rows
    const __nv_bfloat16* vh = g_vh + (size_t)bh * SS * KK;
    const __nv_bfloat16* vl = g_vl + (size_t)bh * SS * KK;
    float s = 0.f;
    for (int r = part * 256; r < part * 256 + 256; r++)
        s += __bfloat162float(vh[(size_t)r * KK + k]) +
             __bfloat162float(vl[(size_t)r * KK + k]);
    __shared__ float red[256];
    red[tid] = s;
    __syncthreads();
    if (part == 0)
        g_sv[bh * KK + k] = red[k] + red[64 + k] + red[128 + k] + red[192 + k];
}

// ---------------------------------------------------------------------------
// shared mma mainloop (R11 2-stage KC=32), templated on term count.
// NT=3: d += Ah·Bh + Ah·Bl + Al·Bh.   NT=1: d += Ah·Bh (half the loads too).
// ---------------------------------------------------------------------------
struct MmaCtx {
    float d[2][8][4];
    uint32_t aHi[2], aLo[2], bHi[4], bLo[4];
};

template <int NT>
__device__ __forceinline__ void mma_mainloop(
    MmaCtx& cx, uint32_t sb,
    const __nv_bfloat16* srcAh, const __nv_bfloat16* srcAl,
    const __nv_bfloat16* srcBh, const __nv_bfloat16* srcBl)
{
    const int tid = threadIdx.x;
    const int wid = tid >> 5, lane = tid & 31;
    const int wm = (wid & 3) * 32, wn = (wid >> 2) * 64;

    #pragma unroll
    for (int mb = 0; mb < 2; mb++) {
        uint32_t ro = (uint32_t)(wm + mb * 16 + (lane & 15)) * ROW_B + (lane >> 4) * 16;
        cx.aHi[mb] = sb + ro;
        cx.aLo[mb] = sb + ARR_B + ro;
    }
    #pragma unroll
    for (int p = 0; p < 4; p++) {
        uint32_t ro = (uint32_t)(wn + p * 16 + (lane >> 4) * 8 + (lane & 7)) * ROW_B
                    + ((lane >> 3) & 1) * 16;
        cx.bHi[p] = sb + B_HI + ro;
        cx.bLo[p] = sb + B_LO + ro;
    }
    #pragma unroll
    for (int mb = 0; mb < 2; mb++)
        #pragma unroll
        for (int nb = 0; nb < 8; nb++)
            #pragma unroll
            for (int e = 0; e < 4; e++) cx.d[mb][nb][e] = 0.f;

    // loader: NT=3 -> 4 arrays (Ah,Al,Bh,Bl); NT=1 -> 2 arrays (Ah,Bh)
    constexpr int NCH = (NT == 3) ? 8 : 4;
    auto load_stage = [&](uint32_t stb, int k0) {
        #pragma unroll
        for (int i = 0; i < NCH; i++) {
            int idx = tid + i * 256;
            int a = idx >> 9, ci = idx & 511, r = ci >> 2, cc = ci & 3;
            const __nv_bfloat16* s;
            uint32_t aoff;
            if (NT == 3) {
                s = (a == 0) ? srcAh : (a == 1) ? srcAl : (a == 2) ? srcBh : srcBl;
                aoff = (uint32_t)a * ARR_B;
            } else {
                s = (a == 0) ? srcAh : srcBh;
                aoff = (a == 0) ? 0u : (uint32_t)B_HI;
            }
            cpasync16(stb + aoff + (uint32_t)(r * ROW_B + cc * 16),
                      s + (size_t)r * DD + k0 + cc * 8);
        }
        CP_COMMIT();
    };

    load_stage(sb, 0);

    for (int it = 0; it < 16; it++) {
        if (it + 1 < 16) {
            load_stage(sb + (uint32_t)((it + 1) & 1) * STAGE_B, (it + 1) * 32);
            CP_WAIT(1);
        } else {
            CP_WAIT(0);
        }
        __syncthreads();

        const uint32_t so = (uint32_t)(it & 1) * STAGE_B;
        #pragma unroll
        for (int ks = 0; ks < 2; ks++) {
            const uint32_t off = so + ks * 32;
            unsigned ah[2][4], al[2][4];
            #pragma unroll
            for (int mb = 0; mb < 2; mb++) {
                ldsm4(ah[mb], cx.aHi[mb] + off);
                if (NT == 3) ldsm4(al[mb], cx.aLo[mb] + off);
            }
            #pragma unroll
            for (int p = 0; p < 4; p++) {
                unsigned tbh[4], tbl[4];
                ldsm4(tbh, cx.bHi[p] + off);
                if (NT == 3) ldsm4(tbl, cx.bLo[p] + off);
                #pragma unroll
                for (int mb = 0; mb < 2; mb++)
                    #pragma unroll
                    for (int qn = 0; qn < 2; qn++)
                        mma16816(cx.d[mb][2 * p + qn], ah[mb], &tbh[2 * qn]);
                if (NT == 3) {
                    #pragma unroll
                    for (int mb = 0; mb < 2; mb++)
                        #pragma unroll
                        for (int qn = 0; qn < 2; qn++)
                            mma16816(cx.d[mb][2 * p + qn], ah[mb], &tbl[2 * qn]);
                    #pragma unroll
                    for (int mb = 0; mb < 2; mb++)
                        #pragma unroll
                        for (int qn = 0; qn < 2; qn++)
                            mma16816(cx.d[mb][2 * p + qn], al[mb], &tbh[2 * qn]);
                }
            }
        }
        __syncthreads();
    }
}

// ---------------------------------------------------------------------------
// projection + L2 norm -> bf16 outputs in [bh][s][k]
// Q,K: 1-term GEMM.  V: 3-term GEMM.
// ---------------------------------------------------------------------------
__global__ __launch_bounds__(256) void proj_mma()
{
    extern __shared__ __align__(16) char dsm[];
    const uint32_t sb = smem_u32(dsm);

    const int n0 = blockIdx.x * 128;
    const int m0 = blockIdx.y * 128;
    const int t  = n0 >> 9;
    const int nr = n0 & 511;

    const __nv_bfloat16* srcAh = g_ih + (size_t)t * (SS * BB * DD) + (size_t)m0 * DD;
    const __nv_bfloat16* srcAl = g_il + (size_t)t * (SS * BB * DD) + (size_t)m0 * DD;
    const __nv_bfloat16* srcBh = g_wh + (size_t)t * (DD * DD) + (size_t)nr * DD;
    const __nv_bfloat16* srcBl = g_wl + (size_t)t * (DD * DD) + (size_t)nr * DD;

    __nv_bfloat16* dsth = (t == 0) ? g_qh : (t == 1) ? g_kh : g_vh;
    __nv_bfloat16* dstl = g_vl;
    const bool write_lo = (t == 2);     // only V needs the lo residue

    MmaCtx cx;
    if (t == 2) mma_mainloop<3>(cx, sb, srcAh, srcAl, srcBh, srcBl);
    else        mma_mainloop<1>(cx, sb, srcAh, srcAl, srcBh, srcBl);

    const int tid = threadIdx.x;
    const int wid = tid >> 5, lane = tid & 31;
    const int wm = (wid & 3) * 32, wn = (wid >> 2) * 64;
    const int r0 = lane >> 2, c0 = lane & 3;
    const int h = (nr >> 6) + (wn >> 6);

    #pragma unroll
    for (int mb = 0; mb < 2; mb++) {
        float ssa = 0.f, ssb = 0.f;
        #pragma unroll
        for (int nb = 0; nb < 8; nb++) {
            float* d = cx.d[mb][nb];
            ssa = fmaf(d[0], d[0], fmaf(d[1], d[1], ssa));
            ssb = fmaf(d[2], d[2], fmaf(d[3], d[3], ssb));
        }
        ssa += __shfl_xor_sync(0xffffffffu, ssa, 1);
        ssa += __shfl_xor_sync(0xffffffffu, ssa, 2);
        ssb += __shfl_xor_sync(0xffffffffu, ssb, 1);
        ssb += __shfl_xor_sync(0xffffffffu, ssb, 2);
        float inva = 1.0f / fmaxf(sqrtf(ssa), 1e-12f);
        float invb = 1.0f / fmaxf(sqrtf(ssb), 1e-12f);

        int ma = m0 + wm + mb * 16 + r0;
        int mb2 = ma + 8;
        int ba = ma & 15, sa = ma >> 4;
        int bbb = mb2 & 15, sbb = mb2 >> 4;
        size_t rowA = (((size_t)(ba * HH + h)) * SS + sa) * KK;
        size_t rowB = (((size_t)(bbb * HH + h)) * SS + sbb) * KK;
        #pragma unroll
        for (int nb = 0; nb < 8; nb++) {
            int kk = ((wn & 63) + nb * 8 + 2 * c0);
            float* d = cx.d[mb][nb];
            unsigned hA, lA, hB, lB;
            split2(d[0] * inva, d[1] * inva, hA, lA);
            split2(d[2] * invb, d[3] * invb, hB, lB);
            *(unsigned*)&dsth[rowA + kk] = hA;
            *(unsigned*)&dsth[rowB + kk] = hB;
            if (write_lo) {
                *(unsigned*)&dstl[rowA + kk] = lA;
                *(unsigned*)&dstl[rowB + kk] = lB;
            }
        }
    }
}

// ---------------------------------------------------------------------------
// output projection: out[m][n] fp32 (3-term)
// ---------------------------------------------------------------------------
__global__ __launch_bounds__(256) void outproj_mma(float* __restrict__ out)
{
    extern __shared__ __align__(16) char dsm[];
    const uint32_t sb = smem_u32(dsm);

    const int n0 = blockIdx.x * 128;
    const int m0 = blockIdx.y * 128;

    MmaCtx cx;
    mma_mainloop<3>(cx, sb, g_ath + (size_t)m0 * DD, g_atl + (size_t)m0 * DD,
                    g_oh + (size_t)n0 * DD, g_ol + (size_t)n0 * DD);

    const int tid = threadIdx.x;
    const int wid = tid >> 5, lane = tid & 31;
    const int wm = (wid & 3) * 32, wn = (wid >> 2) * 64;
    const int r0 = lane >> 2, c0 = lane & 3;

    #pragma unroll
    for (int mb = 0; mb < 2; mb++) {
        int ma = m0 + wm + mb * 16 + r0;
        float* pa = out + (size_t)ma * DD;
        float* pb = out + (size_t)(ma + 8) * DD;
        #pragma unroll
        for (int nb = 0; nb < 8; nb++) {
            int n = n0 + wn + nb * 8 + 2 * c0;
            float* d = cx.d[mb][nb];
            *(float2*)&pa[n] = make_float2(d[0], d[1]);
            *(float2*)&pb[n] = make_float2(d[2], d[3]);
        }
    }
}

// ---------------------------------------------------------------------------
// attention via mma.sync, P = 1 + P' decomposition, Vh-only PV:
//   O = SV + P'h·Vh,  l = 1024 + sum(p').
//   SV is exact (fp32 column sums of vh+vl), so V's bf16 rounding only enters
//   through the small P' weights (|p'|<=0.13) -> ~1e-4 relative.
//   Per chunk/warp: 32 score + 32 PV MMAs; smem stage = kh,vh only.
// ---------------------------------------------------------------------------
#define AT_ROW   144
#define AT_ARR   (64 * AT_ROW)        // 9216
#define AT_STAGE (2 * AT_ARR)         // 18432 (kh | vh)
#define AT_QOFF  (3 * AT_STAGE)       // 55296
#define ATT_SMEM (AT_QOFF + 128 * AT_ROW)   // 73728

__global__ __launch_bounds__(256, 2) void attn_mma()
{
    extern __shared__ __align__(16) char dsm[];
    const uint32_t sb = smem_u32(dsm);

    const int tid = threadIdx.x, wid = tid >> 5, lane = tid & 31;
    const int s0 = blockIdx.x * 128;
    const int bh = blockIdx.y;
    const int b = bh >> 3, h = bh & 7;

    const __nv_bfloat16* qh = g_qh + (size_t)bh * SS * KK + (size_t)s0 * KK;
    const __nv_bfloat16* kh = g_kh + (size_t)bh * SS * KK;
    const __nv_bfloat16* vh = g_vh + (size_t)bh * SS * KK;

    // chunk loader: kh,vh tiles of 64 rows x 64 bf16 (4 chunks/thread)
    auto load_chunk = [&](uint32_t stb, int t0) {
        #pragma unroll
        for (int i = 0; i < 4; i++) {
            int idx = tid + i * 256;
            int a = idx >> 9, ci = idx & 511, r = ci >> 3, c = ci & 7;
            const __nv_bfloat16* s = (a == 0) ? kh : vh;
            cpasync16(stb + a * AT_ARR + (uint32_t)(r * AT_ROW + c * 16),
                      s + (size_t)(t0 + r) * KK + c * 8);
        }
    };

    // group 0: Q tile (hi only), 128 rows x 64 bf16
    #pragma unroll
    for (int i = 0; i < 4; i++) {
        int idx = tid + i * 256;
        int r = idx >> 3, c = idx & 7;
        cpasync16(sb + AT_QOFF + (uint32_t)(r * AT_ROW + c * 16),
                  qh + (size_t)r * KK + c * 8);
    }
    CP_COMMIT();
    // groups 1,2: chunks 0,1
    load_chunk(sb, 0); CP_COMMIT();
    load_chunk(sb + AT_STAGE, 64); CP_COMMIT();

    CP_WAIT(2);          // Q ready
    __syncthreads();
    unsigned qf[4][4];
    const int wq0 = wid * 16;
    #pragma unroll
    for (int ks = 0; ks < 4; ks++)
        ldsm4(qf[ks], sb + AT_QOFF + (uint32_t)((wq0 + (lane & 15)) * AT_ROW)
                        + ks * 32 + (lane >> 4) * 16);

    float o[8][4] = {};
    float l0 = 0.f, l1 = 0.f;     // sums of p'

    for (int c = 0; c < 16; c++) {
        if (c < 15) { CP_WAIT(1); } else { CP_WAIT(0); }
        __syncthreads();                 // all warps done with stage (c+2)%3's prior use
        if (c + 2 < 16) {
            load_chunk(sb + (uint32_t)((c + 2) % 3) * AT_STAGE, (c + 2) * 64);
            CP_COMMIT();
        }
        const uint32_t so = sb + (uint32_t)(c % 3) * AT_STAGE;

        // scores: Qh . Kh — p-pairs: 4 independent accumulators in flight
        float sc[8][4] = {};
        #pragma unroll
        for (int ks = 0; ks < 4; ks++) {
            #pragma unroll
            for (int pp = 0; pp < 2; pp++) {
                unsigned kh4a[4], kh4b[4];
                uint32_t roa = (uint32_t)(((2 * pp) * 16 + (lane >> 4) * 8 + (lane & 7)) * AT_ROW)
                             + ks * 32 + ((lane >> 3) & 1) * 16;
                uint32_t rob = roa + 16 * AT_ROW;
                ldsm4(kh4a, so + roa);
                ldsm4(kh4b, so + rob);
                mma16816(sc[4 * pp + 0], qf[ks], &kh4a[0]);
                mma16816(sc[4 * pp + 1], qf[ks], &kh4a[2]);
                mma16816(sc[4 * pp + 2], qf[ks], &kh4b[0]);
                mma16816(sc[4 * pp + 3], qf[ks], &kh4b[2]);
            }
        }

        // p' = exp(s/8) - 1 (bounded, no running max), accumulate sum(p')
        float ev[8][4];
        #pragma unroll
        for (int nt = 0; nt < 8; nt++) {
            ev[nt][0] = __expf(sc[nt][0] * 0.125f) - 1.0f;
            ev[nt][1] = __expf(sc[nt][1] * 0.125f) - 1.0f;
            ev[nt][2] = __expf(sc[nt][2] * 0.125f) - 1.0f;
            ev[nt][3] = __expf(sc[nt][3] * 0.125f) - 1.0f;
            l0 += ev[nt][0] + ev[nt][1];
            l1 += ev[nt][2] + ev[nt][3];
        }

        // O += P'h·Vh — p-pairs (4 indep accs in flight)
        #pragma unroll
        for (int ts = 0; ts < 4; ts++) {
            unsigned ph[4];
            ph[0] = bpack(ev[2 * ts][0],     ev[2 * ts][1]);
            ph[1] = bpack(ev[2 * ts][2],     ev[2 * ts][3]);
            ph[2] = bpack(ev[2 * ts + 1][0], ev[2 * ts + 1][1]);
            ph[3] = bpack(ev[2 * ts + 1][2], ev[2 * ts + 1][3]);
            #pragma unroll
            for (int pp = 0; pp < 2; pp++) {
                uint32_t roa = (uint32_t)((ts * 16 + ((lane >> 3) & 1) * 8 + (lane & 7)) * AT_ROW)
                             + ((2 * pp) * 16 + (lane >> 4) * 8) * 2;
                uint32_t rob = roa + 32;
                unsigned vh4a[4], vh4b[4];
                ldsm4t(vh4a, so + AT_ARR + roa);
                ldsm4t(vh4b, so + AT_ARR + rob);
                mma16816(o[4 * pp + 0], ph, &vh4a[0]);
                mma16816(o[4 * pp + 1], ph, &vh4a[2]);
                mma16816(o[4 * pp + 2], ph, &vh4b[0]);
                mma16816(o[4 * pp + 3], ph, &vh4b[2]);
            }
        }
    }

    // denominators: l = 1024 + sum(p'); reduce col-pairs across the quad
    l0 += __shfl_xor_sync(0xffffffffu, l0, 1);
    l0 += __shfl_xor_sync(0xffffffffu, l0, 2);
    l1 += __shfl_xor_sync(0xffffffffu, l1, 1);
    l1 += __shfl_xor_sync(0xffffffffu, l1, 2);
    float inv0 = 1.0f / (1024.0f + l0);
    float inv1 = 1.0f / (1024.0f + l1);

    const int r0 = lane >> 2, c0 = lane & 3;
    int sA = s0 + wq0 + r0;
    size_t mA = ((size_t)sA * BB + b) * (HH * KK);
    size_t mB = ((size_t)(sA + 8) * BB + b) * (HH * KK);
    const float* svp = g_sv + bh * KK;
    #pragma unroll
    for (int nk = 0; nk < 8; nk++) {
        int kk = nk * 8 + 2 * c0;
        int j = h * KK + kk;
        float2 sv = *(const float2*)&svp[kk];
        unsigned h0, lo0, h1, lo1;
        split2((sv.x + o[nk][0]) * inv0, (sv.y + o[nk][1]) * inv0, h0, lo0);
        split2((sv.x + o[nk][2]) * inv1, (sv.y + o[nk][3]) * inv1, h1, lo1);
        *(unsigned*)&g_ath[mA + j] = h0;
        *(unsigned*)&g_atl[mA + j] = lo0;
        *(unsigned*)&g_ath[mB + j] = h1;
        *(unsigned*)&g_atl[mB + j] = lo1;
    }
}

// ---------------------------------------------------------------------------
extern "C" void kernel_launch(void* const* d_in, const int* in_sizes, int n_in,
                              void* d_out, int out_size)
{
    const float* q    = (const float*)d_in[0];
    const float* k    = (const float*)d_in[1];
    const float* v    = (const float*)d_in[2];
    const float* WQ   = (const float*)d_in[3];
    const float* WK   = (const float*)d_in[4];
    const float* WV   = (const float*)d_in[5];
    const float* Wout = (const float*)d_in[6];
    float* out = (float*)d_out;

    cudaFuncSetAttribute(proj_mma,
                         cudaFuncAttributeMaxDynamicSharedMemorySize, MMA_SMEM);
    cudaFuncSetAttribute(outproj_mma,
                         cudaFuncAttributeMaxDynamicSharedMemorySize, MMA_SMEM);
    cudaFuncSetAttribute(attn_mma,
                         cudaFuncAttributeMaxDynamicSharedMemorySize, ATT_SMEM);

    cvt_all<<<dim3(1024, 1, 7), 256>>>((const float4*)q, (const float4*)k,
                                       (const float4*)v, (const float4*)WQ,
                                       (const float4*)WK, (const float4*)WV,
                                       (const float4*)Wout);
    proj_mma<<<dim3(12, 128), 256, MMA_SMEM>>>();
    sum_v<<<BB * HH, 256>>>();
    attn_mma<<<dim3(SS / 128, BB * HH), 256, ATT_SMEM>>>();
    outproj_mma<<<dim3(4, 128), 256, MMA_SMEM>>>(out);
}